// round 3
// baseline (speedup 1.0000x reference)
#include <cuda_runtime.h>

typedef unsigned long long u64;

#define NB 2
#define NH 12
#define SQ 1024
#define DK 64
#define DM 768

// ---------------- scratch (static device globals; no allocation) ----------------
__device__ float g_q[NB*NH*SQ*DK];                 // pre-scaled by 1/64
__device__ float g_k[NB*NH*SQ*DK];
__device__ float g_v[NB*NH*SQ*DK];
__device__ float g_scores[(size_t)NB*NH*SQ*SQ];    // scores, then probs (in place)
__device__ float g_attn[NB*SQ*DM];

// ---------------- packed f32x2 helpers ----------------
__device__ __forceinline__ u64 fpack(float x, float y){
    u64 r; asm("mov.b64 %0,{%1,%2};" : "=l"(r) : "f"(x), "f"(y)); return r;
}
__device__ __forceinline__ u64 ffma2(u64 a, u64 b, u64 c){
    u64 d; asm("fma.rn.f32x2 %0,%1,%2,%3;" : "=l"(d) : "l"(a), "l"(b), "l"(c)); return d;
}
__device__ __forceinline__ float2 funpack(u64 v){
    float x, y; asm("mov.b64 {%0,%1},%2;" : "=f"(x), "=f"(y) : "l"(v)); return make_float2(x, y);
}

// =====================================================================
// K1: QKV projections. grid (16, 12, 3)
// =====================================================================
__global__ __launch_bounds__(256) void k_proj(
    const float* __restrict__ Xq, const float* __restrict__ Xk, const float* __restrict__ Xv,
    const float* __restrict__ Wq, const float* __restrict__ Wk, const float* __restrict__ Wv,
    const float* __restrict__ bq, const float* __restrict__ bk, const float* __restrict__ bv)
{
    const int z = blockIdx.z;
    const float* X    = (z == 0) ? Xq : (z == 1) ? Xk : Xv;
    const float* W    = (z == 0) ? Wq : (z == 1) ? Wk : Wv;
    const float* bias = (z == 0) ? bq : (z == 1) ? bk : bv;
    float* out        = (z == 0) ? g_q : (z == 1) ? g_k : g_v;
    const float scale = (z == 0) ? (1.0f / 64.0f) : 1.0f;

    __shared__ __align__(16) float As[16][128];
    __shared__ __align__(16) float Bs[16][64];

    const int tid = threadIdx.x;
    const int tx = tid & 15, ty = tid >> 4;
    const int m0 = blockIdx.x * 128;
    const int h  = blockIdx.y;
    const int n0 = h * 64;

    u64 acc[8][2];
    #pragma unroll
    for (int i = 0; i < 8; i++) { acc[i][0] = 0ull; acc[i][1] = 0ull; }

    for (int k0 = 0; k0 < DM; k0 += 16) {
        #pragma unroll
        for (int it = 0; it < 2; it++) {
            int f = tid + it * 256;
            int m = f >> 2;
            int kk = (f & 3) * 4;
            float4 a4 = *(const float4*)(X + (size_t)(m0 + m) * DM + k0 + kk);
            As[kk + 0][m] = a4.x; As[kk + 1][m] = a4.y;
            As[kk + 2][m] = a4.z; As[kk + 3][m] = a4.w;
        }
        {
            int kk = tid >> 4;
            int nn = (tid & 15) * 4;
            *(float4*)&Bs[kk][nn] = *(const float4*)(W + (size_t)(k0 + kk) * DM + n0 + nn);
        }
        __syncthreads();
        #pragma unroll
        for (int k = 0; k < 16; k++) {
            float4 a0 = *(const float4*)&As[k][ty * 8];
            float4 a1 = *(const float4*)&As[k][ty * 8 + 4];
            ulonglong2 bu = *(const ulonglong2*)&Bs[k][tx * 4];
            float a[8] = {a0.x, a0.y, a0.z, a0.w, a1.x, a1.y, a1.z, a1.w};
            #pragma unroll
            for (int i = 0; i < 8; i++) {
                u64 ad = fpack(a[i], a[i]);
                acc[i][0] = ffma2(ad, bu.x, acc[i][0]);
                acc[i][1] = ffma2(ad, bu.y, acc[i][1]);
            }
        }
        __syncthreads();
    }

    float4 bb = *(const float4*)(bias + n0 + tx * 4);
    #pragma unroll
    for (int i = 0; i < 8; i++) {
        int m = m0 + ty * 8 + i;
        int b = m >> 10;
        int s = m & (SQ - 1);
        float2 p0 = funpack(acc[i][0]);
        float2 p1 = funpack(acc[i][1]);
        float4 o;
        o.x = (p0.x + bb.x) * scale;
        o.y = (p0.y + bb.y) * scale;
        o.z = (p1.x + bb.z) * scale;
        o.w = (p1.y + bb.w) * scale;
        *(float4*)(out + ((size_t)((b * NH + h) * SQ + s)) * DK + tx * 4) = o;
    }
}

// =====================================================================
// K2: scores = q @ k^T per (b,h). grid (8, 8, 24), dyn smem 67584 B
// =====================================================================
__global__ __launch_bounds__(256) void k_qk()
{
    extern __shared__ __align__(16) float sm[];
    float (*As)[132] = (float(*)[132])sm;
    float (*Bs)[132] = (float(*)[132])(sm + 64 * 132);

    const int bh = blockIdx.z;
    const float* A  = g_q + (size_t)bh * SQ * DK;
    const float* Bm = g_k + (size_t)bh * SQ * DK;
    float* C = g_scores + (size_t)bh * SQ * SQ;

    const int m0 = blockIdx.x * 128;
    const int n0 = blockIdx.y * 128;
    const int tid = threadIdx.x;
    const int tx = tid & 15, ty = tid >> 4;

    #pragma unroll
    for (int it = 0; it < 8; it++) {
        int f = tid + it * 256;
        int m  = f >> 4;
        int d4 = (f & 15) * 4;
        float4 va = *(const float4*)(A  + (size_t)(m0 + m) * DK + d4);
        float4 vb = *(const float4*)(Bm + (size_t)(n0 + m) * DK + d4);
        As[d4 + 0][m] = va.x; As[d4 + 1][m] = va.y; As[d4 + 2][m] = va.z; As[d4 + 3][m] = va.w;
        Bs[d4 + 0][m] = vb.x; Bs[d4 + 1][m] = vb.y; Bs[d4 + 2][m] = vb.z; Bs[d4 + 3][m] = vb.w;
    }
    __syncthreads();

    u64 acc[8][4];
    #pragma unroll
    for (int i = 0; i < 8; i++)
        #pragma unroll
        for (int j = 0; j < 4; j++) acc[i][j] = 0ull;

    #pragma unroll 4
    for (int d = 0; d < 64; d++) {
        float4 a0 = *(const float4*)&As[d][ty * 8];
        float4 a1 = *(const float4*)&As[d][ty * 8 + 4];
        ulonglong2 b0 = *(const ulonglong2*)&Bs[d][tx * 8];
        ulonglong2 b1 = *(const ulonglong2*)&Bs[d][tx * 8 + 4];
        float a[8] = {a0.x, a0.y, a0.z, a0.w, a1.x, a1.y, a1.z, a1.w};
        #pragma unroll
        for (int i = 0; i < 8; i++) {
            u64 ad = fpack(a[i], a[i]);
            acc[i][0] = ffma2(ad, b0.x, acc[i][0]);
            acc[i][1] = ffma2(ad, b0.y, acc[i][1]);
            acc[i][2] = ffma2(ad, b1.x, acc[i][2]);
            acc[i][3] = ffma2(ad, b1.y, acc[i][3]);
        }
    }

    #pragma unroll
    for (int i = 0; i < 8; i++) {
        float2 p0 = funpack(acc[i][0]);
        float2 p1 = funpack(acc[i][1]);
        float2 p2 = funpack(acc[i][2]);
        float2 p3 = funpack(acc[i][3]);
        float* dst = C + (size_t)(m0 + ty * 8 + i) * SQ + n0 + tx * 8;
        *(float4*)(dst)     = make_float4(p0.x, p0.y, p1.x, p1.y);
        *(float4*)(dst + 4) = make_float4(p2.x, p2.y, p3.x, p3.y);
    }
}

// =====================================================================
// K3 (fused): per (b,q): scores += q . relation_k, then softmax, write probs.
// All 12 head-rows live in smem. grid (1024, 2), dyn smem 87040 B.
// smem layout: ss[12*1024] | rks[128][68] | qs[12*64]
// =====================================================================
__global__ __launch_bounds__(256) void k_qrel_sm(const float* __restrict__ relk)
{
    extern __shared__ __align__(16) float sm[];
    float* ss = sm;                                        // 12288 floats
    float (*rks)[68] = (float(*)[68])(sm + NH * SQ);       // 8704 floats
    float* qs = sm + NH * SQ + 128 * 68;                   // 768 floats

    const int b = blockIdx.y, q = blockIdx.x;
    const int tid = threadIdx.x;

    // load q rows (12 heads x 64)
    if (tid < 192) {
        int hh = tid >> 4;
        int d4 = (tid & 15) * 4;
        *(float4*)&qs[hh * DK + d4] =
            *(const float4*)(g_q + ((size_t)((b * NH + hh) * SQ + q)) * DK + d4);
    }
    // load raw qk scores for all 12 heads (3072 float4)
    #pragma unroll
    for (int it = 0; it < 12; it++) {
        int f = tid + it * 256;
        int hh = f >> 8;
        int k4 = (f & 255) * 4;
        *(float4*)&ss[hh * SQ + k4] =
            *(const float4*)(g_scores + ((size_t)((b * NH + hh) * SQ + q)) * SQ + k4);
    }

    const int klocal = tid & 127;
    const int hg = tid >> 7;                  // 0/1 -> heads [hg*6, hg*6+6)
    const float* relbase = relk + ((size_t)(b * SQ + q)) * SQ * DK;

    for (int kt = 0; kt < SQ; kt += 128) {
        __syncthreads();
        #pragma unroll
        for (int it = 0; it < 8; it++) {
            int f = tid + it * 256;
            int kk = f >> 4;
            int d4 = (f & 15) * 4;
            *(float4*)&rks[kk][d4] = *(const float4*)(relbase + (size_t)(kt + kk) * DK + d4);
        }
        __syncthreads();

        u64 acc2[6] = {0ull, 0ull, 0ull, 0ull, 0ull, 0ull};
        #pragma unroll
        for (int d4 = 0; d4 < 64; d4 += 4) {
            ulonglong2 r = *(const ulonglong2*)&rks[klocal][d4];
            #pragma unroll
            for (int j = 0; j < 6; j++) {
                ulonglong2 qv = *(const ulonglong2*)&qs[(hg * 6 + j) * DK + d4];
                acc2[j] = ffma2(qv.x, r.x, acc2[j]);
                acc2[j] = ffma2(qv.y, r.y, acc2[j]);
            }
        }
        #pragma unroll
        for (int j = 0; j < 6; j++) {
            float2 p = funpack(acc2[j]);
            ss[(hg * 6 + j) * SQ + kt + klocal] += p.x + p.y;
        }
    }
    __syncthreads();

    // softmax per head-row in smem, write probs to g_scores
    const int warp = tid >> 5;
    const int lane = tid & 31;
    for (int r = warp; r < NH; r += 8) {
        float* p = ss + r * SQ;
        float4 v[8];
        float mx = -3.4e38f;
        #pragma unroll
        for (int j = 0; j < 8; j++) {
            v[j] = *(float4*)(p + lane * 4 + j * 128);
            mx = fmaxf(mx, fmaxf(fmaxf(v[j].x, v[j].y), fmaxf(v[j].z, v[j].w)));
        }
        #pragma unroll
        for (int o = 16; o > 0; o >>= 1) mx = fmaxf(mx, __shfl_xor_sync(0xffffffffu, mx, o));

        float s = 0.f;
        #pragma unroll
        for (int j = 0; j < 8; j++) {
            v[j].x = __expf(v[j].x - mx);
            v[j].y = __expf(v[j].y - mx);
            v[j].z = __expf(v[j].z - mx);
            v[j].w = __expf(v[j].w - mx);
            s += v[j].x + v[j].y + v[j].z + v[j].w;
        }
        #pragma unroll
        for (int o = 16; o > 0; o >>= 1) s += __shfl_xor_sync(0xffffffffu, s, o);
        const float inv = 1.0f / s;

        float* dst = g_scores + ((size_t)((b * NH + r) * SQ + q)) * SQ;
        #pragma unroll
        for (int j = 0; j < 8; j++) {
            v[j].x *= inv; v[j].y *= inv; v[j].z *= inv; v[j].w *= inv;
            *(float4*)(dst + lane * 4 + j * 128) = v[j];
        }
    }
}

// =====================================================================
// K5: wv = probs @ v per (b,h). grid (8, 24). Writes g_attn.
// =====================================================================
__global__ __launch_bounds__(256) void k_wv()
{
    __shared__ __align__(16) float As[32][132];
    __shared__ __align__(16) float Bs[32][68];

    const int bh = blockIdx.y;
    const int b = bh / NH, h = bh % NH;
    const float* A  = g_scores + (size_t)bh * SQ * SQ;
    const float* Bv = g_v + (size_t)bh * SQ * DK;

    const int m0 = blockIdx.x * 128;
    const int tid = threadIdx.x;
    const int tx = tid & 15, ty = tid >> 4;

    u64 acc[8][2];
    #pragma unroll
    for (int i = 0; i < 8; i++) { acc[i][0] = 0ull; acc[i][1] = 0ull; }

    for (int k0 = 0; k0 < SQ; k0 += 32) {
        #pragma unroll
        for (int it = 0; it < 4; it++) {
            int f = tid + it * 256;
            int m  = f >> 3;
            int k4 = (f & 7) * 4;
            float4 a4 = *(const float4*)(A + (size_t)(m0 + m) * SQ + k0 + k4);
            As[k4 + 0][m] = a4.x; As[k4 + 1][m] = a4.y;
            As[k4 + 2][m] = a4.z; As[k4 + 3][m] = a4.w;
        }
        #pragma unroll
        for (int it = 0; it < 2; it++) {
            int f = tid + it * 256;
            int kk = f >> 4;
            int d4 = (f & 15) * 4;
            *(float4*)&Bs[kk][d4] = *(const float4*)(Bv + (size_t)(k0 + kk) * DK + d4);
        }
        __syncthreads();
        #pragma unroll 8
        for (int k = 0; k < 32; k++) {
            float4 a0 = *(const float4*)&As[k][ty * 8];
            float4 a1 = *(const float4*)&As[k][ty * 8 + 4];
            ulonglong2 bu = *(const ulonglong2*)&Bs[k][tx * 4];
            float a[8] = {a0.x, a0.y, a0.z, a0.w, a1.x, a1.y, a1.z, a1.w};
            #pragma unroll
            for (int i = 0; i < 8; i++) {
                u64 ad = fpack(a[i], a[i]);
                acc[i][0] = ffma2(ad, bu.x, acc[i][0]);
                acc[i][1] = ffma2(ad, bu.y, acc[i][1]);
            }
        }
        __syncthreads();
    }

    #pragma unroll
    for (int i = 0; i < 8; i++) {
        int m = m0 + ty * 8 + i;
        float2 p0 = funpack(acc[i][0]);
        float2 p1 = funpack(acc[i][1]);
        float4 o = make_float4(p0.x, p0.y, p1.x, p1.y);
        *(float4*)(g_attn + (size_t)(b * SQ + m) * DM + h * DK + tx * 4) = o;
    }
}

// =====================================================================
// K6: g_attn[b,q,h*64+d] += sum_k probs[b,h,q,k] * relation_v[b,q,k,d]
// relV chunk stored TRANSPOSED in smem (rvt[d][k], pad 132) so each
// thread pulls 4 k-positions with one LDS.128. grid (1024, 2).
// =====================================================================
__global__ __launch_bounds__(256) void k_wrel(const float* __restrict__ relv)
{
    __shared__ __align__(16) float rvt[64][132];
    __shared__ __align__(16) float ps[NH][128];

    const int b = blockIdx.y, q = blockIdx.x;
    const int tid = threadIdx.x;
    const int d  = tid & 63;
    const int hg = tid >> 6;                   // 0..3 -> heads {hg, hg+4, hg+8}
    const float* relbase = relv + ((size_t)(b * SQ + q)) * SQ * DK;

    u64 acc2[3] = {0ull, 0ull, 0ull};

    for (int kt = 0; kt < SQ; kt += 128) {
        __syncthreads();
        #pragma unroll
        for (int it = 0; it < 8; it++) {
            int f = tid + it * 256;
            int kk = f >> 4;
            int d4 = (f & 15) * 4;
            float4 rv = *(const float4*)(relbase + (size_t)(kt + kk) * DK + d4);
            rvt[d4 + 0][kk] = rv.x;
            rvt[d4 + 1][kk] = rv.y;
            rvt[d4 + 2][kk] = rv.z;
            rvt[d4 + 3][kk] = rv.w;
        }
        #pragma unroll
        for (int it = 0; it < 2; it++) {
            int f = tid + it * 256;
            if (f < 384) {
                int hh = f >> 5;
                int k4 = (f & 31) * 4;
                *(float4*)&ps[hh][k4] =
                    *(const float4*)(g_scores + ((size_t)((b * NH + hh) * SQ + q)) * SQ + kt + k4);
            }
        }
        __syncthreads();

        #pragma unroll 4
        for (int k4 = 0; k4 < 128; k4 += 4) {
            float4 rv4 = *(const float4*)&rvt[d][k4];
            u64 rv01 = fpack(rv4.x, rv4.y);
            u64 rv23 = fpack(rv4.z, rv4.w);
            #pragma unroll
            for (int j = 0; j < 3; j++) {
                ulonglong2 pu = *(const ulonglong2*)&ps[hg + 4 * j][k4];
                acc2[j] = ffma2(pu.x, rv01, acc2[j]);
                acc2[j] = ffma2(pu.y, rv23, acc2[j]);
            }
        }
    }

    #pragma unroll
    for (int j = 0; j < 3; j++) {
        int h = hg + 4 * j;
        float2 p = funpack(acc2[j]);
        float* dst = g_attn + (size_t)(b * SQ + q) * DM + h * DK + d;
        *dst += p.x + p.y;
    }
}

// =====================================================================
// K7: output projection. grid (16, 12).
// =====================================================================
__global__ __launch_bounds__(256) void k_out(
    const float* __restrict__ Wo, const float* __restrict__ bo, float* __restrict__ out)
{
    __shared__ __align__(16) float As[16][128];
    __shared__ __align__(16) float Bs[16][64];

    const int tid = threadIdx.x;
    const int tx = tid & 15, ty = tid >> 4;
    const int m0 = blockIdx.x * 128;
    const int n0 = blockIdx.y * 64;

    u64 acc[8][2];
    #pragma unroll
    for (int i = 0; i < 8; i++) { acc[i][0] = 0ull; acc[i][1] = 0ull; }

    for (int k0 = 0; k0 < DM; k0 += 16) {
        #pragma unroll
        for (int it = 0; it < 2; it++) {
            int f = tid + it * 256;
            int m = f >> 2;
            int kk = (f & 3) * 4;
            float4 a4 = *(const float4*)(g_attn + (size_t)(m0 + m) * DM + k0 + kk);
            As[kk + 0][m] = a4.x; As[kk + 1][m] = a4.y;
            As[kk + 2][m] = a4.z; As[kk + 3][m] = a4.w;
        }
        {
            int kk = tid >> 4;
            int nn = (tid & 15) * 4;
            *(float4*)&Bs[kk][nn] = *(const float4*)(Wo + (size_t)(k0 + kk) * DM + n0 + nn);
        }
        __syncthreads();
        #pragma unroll
        for (int k = 0; k < 16; k++) {
            float4 a0 = *(const float4*)&As[k][ty * 8];
            float4 a1 = *(const float4*)&As[k][ty * 8 + 4];
            ulonglong2 bu = *(const ulonglong2*)&Bs[k][tx * 4];
            float a[8] = {a0.x, a0.y, a0.z, a0.w, a1.x, a1.y, a1.z, a1.w};
            #pragma unroll
            for (int i = 0; i < 8; i++) {
                u64 ad = fpack(a[i], a[i]);
                acc[i][0] = ffma2(ad, bu.x, acc[i][0]);
                acc[i][1] = ffma2(ad, bu.y, acc[i][1]);
            }
        }
        __syncthreads();
    }

    float4 bb = *(const float4*)(bo + n0 + tx * 4);
    #pragma unroll
    for (int i = 0; i < 8; i++) {
        int m = m0 + ty * 8 + i;
        float2 p0 = funpack(acc[i][0]);
        float2 p1 = funpack(acc[i][1]);
        float4 o = make_float4(p0.x + bb.x, p0.y + bb.y, p1.x + bb.z, p1.y + bb.w);
        *(float4*)(out + (size_t)m * DM + n0 + tx * 4) = o;
    }
}

// =====================================================================
extern "C" void kernel_launch(void* const* d_in, const int* in_sizes, int n_in,
                              void* d_out, int out_size)
{
    const float* queries = (const float*)d_in[0];
    const float* keys    = (const float*)d_in[1];
    const float* values  = (const float*)d_in[2];
    const float* relk    = (const float*)d_in[3];
    const float* relv    = (const float*)d_in[4];
    const float* Wq = (const float*)d_in[5];
    const float* bq = (const float*)d_in[6];
    const float* Wk = (const float*)d_in[7];
    const float* bk = (const float*)d_in[8];
    const float* Wv = (const float*)d_in[9];
    const float* bv = (const float*)d_in[10];
    const float* Wo = (const float*)d_in[11];
    const float* bo = (const float*)d_in[12];
    float* out = (float*)d_out;

    static bool attr_set = false;
    if (!attr_set) {
        cudaFuncSetAttribute(k_qk, cudaFuncAttributeMaxDynamicSharedMemorySize,
                             2 * 64 * 132 * (int)sizeof(float));
        cudaFuncSetAttribute(k_qrel_sm, cudaFuncAttributeMaxDynamicSharedMemorySize,
                             (NH * SQ + 128 * 68 + NH * DK) * (int)sizeof(float));
        attr_set = true;
    }

    // K1: projections
    k_proj<<<dim3(16, 12, 3), 256>>>(queries, keys, values, Wq, Wk, Wv, bq, bk, bv);

    // K2: qk^T -> g_scores
    k_qk<<<dim3(8, 8, NB * NH), 256, 2 * 64 * 132 * sizeof(float)>>>();

    // K3: fused (+= q . relation_k) + softmax -> probs in g_scores
    k_qrel_sm<<<dim3(SQ, NB), 256,
                (NH * SQ + 128 * 68 + NH * DK) * sizeof(float)>>>(relk);

    // K5: probs @ v -> g_attn
    k_wv<<<dim3(8, NB * NH), 256>>>();

    // K6: g_attn += probs @ relation_v
    k_wrel<<<dim3(SQ, NB), 256>>>(relv);

    // K7: output projection
    k_out<<<dim3(16, 12), 256>>>(Wo, bo, out);
}

// round 4
// speedup vs baseline: 1.1531x; 1.1531x over previous
#include <cuda_runtime.h>

typedef unsigned long long u64;

#define NB 2
#define NH 12
#define SQ 1024
#define DK 64
#define DM 768

// ---------------- scratch ----------------
__device__ float g_q[NB*NH*SQ*DK];                 // pre-scaled by 1/64
__device__ float g_k[NB*NH*SQ*DK];
__device__ float g_v[NB*NH*SQ*DK];
__device__ float g_scores[(size_t)NB*NH*SQ*SQ];    // scores, then probs (in place)
__device__ float g_attn[NB*SQ*DM];

// ---------------- packed f32x2 helpers ----------------
__device__ __forceinline__ u64 fpack(float x, float y){
    u64 r; asm("mov.b64 %0,{%1,%2};" : "=l"(r) : "f"(x), "f"(y)); return r;
}
__device__ __forceinline__ u64 ffma2(u64 a, u64 b, u64 c){
    u64 d; asm("fma.rn.f32x2 %0,%1,%2,%3;" : "=l"(d) : "l"(a), "l"(b), "l"(c)); return d;
}
__device__ __forceinline__ float2 funpack(u64 v){
    float x, y; asm("mov.b64 {%0,%1},%2;" : "=f"(x), "=f"(y) : "l"(v)); return make_float2(x, y);
}

// =====================================================================
// K1: QKV projections. grid (16, 12, 3)
// =====================================================================
__global__ __launch_bounds__(256) void k_proj(
    const float* __restrict__ Xq, const float* __restrict__ Xk, const float* __restrict__ Xv,
    const float* __restrict__ Wq, const float* __restrict__ Wk, const float* __restrict__ Wv,
    const float* __restrict__ bq, const float* __restrict__ bk, const float* __restrict__ bv)
{
    const int z = blockIdx.z;
    const float* X    = (z == 0) ? Xq : (z == 1) ? Xk : Xv;
    const float* W    = (z == 0) ? Wq : (z == 1) ? Wk : Wv;
    const float* bias = (z == 0) ? bq : (z == 1) ? bk : bv;
    float* out        = (z == 0) ? g_q : (z == 1) ? g_k : g_v;
    const float scale = (z == 0) ? (1.0f / 64.0f) : 1.0f;

    __shared__ __align__(16) float As[16][128];
    __shared__ __align__(16) float Bs[16][64];

    const int tid = threadIdx.x;
    const int tx = tid & 15, ty = tid >> 4;
    const int m0 = blockIdx.x * 128;
    const int h  = blockIdx.y;
    const int n0 = h * 64;

    u64 acc[8][2];
    #pragma unroll
    for (int i = 0; i < 8; i++) { acc[i][0] = 0ull; acc[i][1] = 0ull; }

    for (int k0 = 0; k0 < DM; k0 += 16) {
        #pragma unroll
        for (int it = 0; it < 2; it++) {
            int f = tid + it * 256;
            int m = f >> 2;
            int kk = (f & 3) * 4;
            float4 a4 = *(const float4*)(X + (size_t)(m0 + m) * DM + k0 + kk);
            As[kk + 0][m] = a4.x; As[kk + 1][m] = a4.y;
            As[kk + 2][m] = a4.z; As[kk + 3][m] = a4.w;
        }
        {
            int kk = tid >> 4;
            int nn = (tid & 15) * 4;
            *(float4*)&Bs[kk][nn] = *(const float4*)(W + (size_t)(k0 + kk) * DM + n0 + nn);
        }
        __syncthreads();
        #pragma unroll
        for (int k = 0; k < 16; k++) {
            float4 a0 = *(const float4*)&As[k][ty * 8];
            float4 a1 = *(const float4*)&As[k][ty * 8 + 4];
            ulonglong2 bu = *(const ulonglong2*)&Bs[k][tx * 4];
            float a[8] = {a0.x, a0.y, a0.z, a0.w, a1.x, a1.y, a1.z, a1.w};
            #pragma unroll
            for (int i = 0; i < 8; i++) {
                u64 ad = fpack(a[i], a[i]);
                acc[i][0] = ffma2(ad, bu.x, acc[i][0]);
                acc[i][1] = ffma2(ad, bu.y, acc[i][1]);
            }
        }
        __syncthreads();
    }

    float4 bb = *(const float4*)(bias + n0 + tx * 4);
    #pragma unroll
    for (int i = 0; i < 8; i++) {
        int m = m0 + ty * 8 + i;
        int b = m >> 10;
        int s = m & (SQ - 1);
        float2 p0 = funpack(acc[i][0]);
        float2 p1 = funpack(acc[i][1]);
        float4 o;
        o.x = (p0.x + bb.x) * scale;
        o.y = (p0.y + bb.y) * scale;
        o.z = (p1.x + bb.z) * scale;
        o.w = (p1.y + bb.w) * scale;
        *(float4*)(out + ((size_t)((b * NH + h) * SQ + s)) * DK + tx * 4) = o;
    }
}

// =====================================================================
// K2: scores = q @ k^T per (b,h). grid (8, 8, 24), dyn smem 67584 B
// =====================================================================
__global__ __launch_bounds__(256) void k_qk()
{
    extern __shared__ __align__(16) float sm[];
    float (*As)[132] = (float(*)[132])sm;
    float (*Bs)[132] = (float(*)[132])(sm + 64 * 132);

    const int bh = blockIdx.z;
    const float* A  = g_q + (size_t)bh * SQ * DK;
    const float* Bm = g_k + (size_t)bh * SQ * DK;
    float* C = g_scores + (size_t)bh * SQ * SQ;

    const int m0 = blockIdx.x * 128;
    const int n0 = blockIdx.y * 128;
    const int tid = threadIdx.x;
    const int tx = tid & 15, ty = tid >> 4;

    #pragma unroll
    for (int it = 0; it < 8; it++) {
        int f = tid + it * 256;
        int m  = f >> 4;
        int d4 = (f & 15) * 4;
        float4 va = *(const float4*)(A  + (size_t)(m0 + m) * DK + d4);
        float4 vb = *(const float4*)(Bm + (size_t)(n0 + m) * DK + d4);
        As[d4 + 0][m] = va.x; As[d4 + 1][m] = va.y; As[d4 + 2][m] = va.z; As[d4 + 3][m] = va.w;
        Bs[d4 + 0][m] = vb.x; Bs[d4 + 1][m] = vb.y; Bs[d4 + 2][m] = vb.z; Bs[d4 + 3][m] = vb.w;
    }
    __syncthreads();

    u64 acc[8][4];
    #pragma unroll
    for (int i = 0; i < 8; i++)
        #pragma unroll
        for (int j = 0; j < 4; j++) acc[i][j] = 0ull;

    #pragma unroll 4
    for (int d = 0; d < 64; d++) {
        float4 a0 = *(const float4*)&As[d][ty * 8];
        float4 a1 = *(const float4*)&As[d][ty * 8 + 4];
        ulonglong2 b0 = *(const ulonglong2*)&Bs[d][tx * 8];
        ulonglong2 b1 = *(const ulonglong2*)&Bs[d][tx * 8 + 4];
        float a[8] = {a0.x, a0.y, a0.z, a0.w, a1.x, a1.y, a1.z, a1.w};
        #pragma unroll
        for (int i = 0; i < 8; i++) {
            u64 ad = fpack(a[i], a[i]);
            acc[i][0] = ffma2(ad, b0.x, acc[i][0]);
            acc[i][1] = ffma2(ad, b0.y, acc[i][1]);
            acc[i][2] = ffma2(ad, b1.x, acc[i][2]);
            acc[i][3] = ffma2(ad, b1.y, acc[i][3]);
        }
    }

    #pragma unroll
    for (int i = 0; i < 8; i++) {
        float2 p0 = funpack(acc[i][0]);
        float2 p1 = funpack(acc[i][1]);
        float2 p2 = funpack(acc[i][2]);
        float2 p3 = funpack(acc[i][3]);
        float* dst = C + (size_t)(m0 + ty * 8 + i) * SQ + n0 + tx * 8;
        *(float4*)(dst)     = make_float4(p0.x, p0.y, p1.x, p1.y);
        *(float4*)(dst + 4) = make_float4(p2.x, p2.y, p3.x, p3.y);
    }
}

// =====================================================================
// K3 (fused): per (b,q): scores += q . relation_k, then softmax -> probs.
// 512 threads (32 warps across 2 CTAs/SM). grid (1024, 2), smem 87040 B.
// =====================================================================
__global__ __launch_bounds__(512) void k_qrel_sm(const float* __restrict__ relk)
{
    extern __shared__ __align__(16) float sm[];
    float* ss = sm;                                        // 12288 floats
    float (*rks)[68] = (float(*)[68])(sm + NH * SQ);       // 8704 floats
    float* qs = sm + NH * SQ + 128 * 68;                   // 768 floats

    const int b = blockIdx.y, q = blockIdx.x;
    const int tid = threadIdx.x;

    // load q rows (12 heads x 64)
    if (tid < 192) {
        int hh = tid >> 4;
        int d4 = (tid & 15) * 4;
        *(float4*)&qs[hh * DK + d4] =
            *(const float4*)(g_q + ((size_t)((b * NH + hh) * SQ + q)) * DK + d4);
    }
    // load raw qk scores for all 12 heads (3072 float4 / 512 threads)
    #pragma unroll
    for (int it = 0; it < 6; it++) {
        int f = tid + it * 512;
        int hh = f >> 8;
        int k4 = (f & 255) * 4;
        *(float4*)&ss[hh * SQ + k4] =
            *(const float4*)(g_scores + ((size_t)((b * NH + hh) * SQ + q)) * SQ + k4);
    }

    const int klocal = tid & 127;
    const int hg = tid >> 7;                  // 0..3 -> heads [hg*3, hg*3+3)
    const float* relbase = relk + ((size_t)(b * SQ + q)) * SQ * DK;

    for (int kt = 0; kt < SQ; kt += 128) {
        __syncthreads();
        #pragma unroll
        for (int it = 0; it < 4; it++) {
            int f = tid + it * 512;
            int kk = f >> 4;
            int d4 = (f & 15) * 4;
            *(float4*)&rks[kk][d4] = *(const float4*)(relbase + (size_t)(kt + kk) * DK + d4);
        }
        __syncthreads();

        u64 acc2[3] = {0ull, 0ull, 0ull};
        #pragma unroll
        for (int d4 = 0; d4 < 64; d4 += 4) {
            ulonglong2 r = *(const ulonglong2*)&rks[klocal][d4];
            #pragma unroll
            for (int j = 0; j < 3; j++) {
                ulonglong2 qv = *(const ulonglong2*)&qs[(hg * 3 + j) * DK + d4];
                acc2[j] = ffma2(qv.x, r.x, acc2[j]);
                acc2[j] = ffma2(qv.y, r.y, acc2[j]);
            }
        }
        #pragma unroll
        for (int j = 0; j < 3; j++) {
            float2 p = funpack(acc2[j]);
            ss[(hg * 3 + j) * SQ + kt + klocal] += p.x + p.y;
        }
    }
    __syncthreads();

    // softmax per head-row in smem, write probs to g_scores
    const int warp = tid >> 5;
    const int lane = tid & 31;
    if (warp < NH) {
        float* p = ss + warp * SQ;
        float4 v[8];
        float mx = -3.4e38f;
        #pragma unroll
        for (int j = 0; j < 8; j++) {
            v[j] = *(float4*)(p + lane * 4 + j * 128);
            mx = fmaxf(mx, fmaxf(fmaxf(v[j].x, v[j].y), fmaxf(v[j].z, v[j].w)));
        }
        #pragma unroll
        for (int o = 16; o > 0; o >>= 1) mx = fmaxf(mx, __shfl_xor_sync(0xffffffffu, mx, o));

        float s = 0.f;
        #pragma unroll
        for (int j = 0; j < 8; j++) {
            v[j].x = __expf(v[j].x - mx);
            v[j].y = __expf(v[j].y - mx);
            v[j].z = __expf(v[j].z - mx);
            v[j].w = __expf(v[j].w - mx);
            s += v[j].x + v[j].y + v[j].z + v[j].w;
        }
        #pragma unroll
        for (int o = 16; o > 0; o >>= 1) s += __shfl_xor_sync(0xffffffffu, s, o);
        const float inv = 1.0f / s;

        float* dst = g_scores + ((size_t)((b * NH + warp) * SQ + q)) * SQ;
        #pragma unroll
        for (int j = 0; j < 8; j++) {
            v[j].x *= inv; v[j].y *= inv; v[j].z *= inv; v[j].w *= inv;
            *(float4*)(dst + lane * 4 + j * 128) = v[j];
        }
    }
}

// =====================================================================
// K5: wv = probs @ v per (b,h). BM=64, BN=64, BK=32, 4x4 microtile.
// grid (16, 24) = 384 CTAs. Writes g_attn.
// =====================================================================
__global__ __launch_bounds__(256) void k_wv()
{
    __shared__ __align__(16) float As[32][68];   // [k][m]
    __shared__ __align__(16) float Bs[32][68];   // [k][d]

    const int bh = blockIdx.y;
    const int b = bh / NH, h = bh % NH;
    const float* A  = g_scores + (size_t)bh * SQ * SQ;
    const float* Bv = g_v + (size_t)bh * SQ * DK;

    const int m0 = blockIdx.x * 64;
    const int tid = threadIdx.x;
    const int tx = tid & 15, ty = tid >> 4;

    u64 acc[4][2];
    #pragma unroll
    for (int i = 0; i < 4; i++) { acc[i][0] = 0ull; acc[i][1] = 0ull; }

    for (int k0 = 0; k0 < SQ; k0 += 32) {
        #pragma unroll
        for (int it = 0; it < 2; it++) {
            int f = tid + it * 256;
            int m  = f >> 3;
            int k4 = (f & 7) * 4;
            float4 a4 = *(const float4*)(A + (size_t)(m0 + m) * SQ + k0 + k4);
            As[k4 + 0][m] = a4.x; As[k4 + 1][m] = a4.y;
            As[k4 + 2][m] = a4.z; As[k4 + 3][m] = a4.w;
        }
        #pragma unroll
        for (int it = 0; it < 2; it++) {
            int f = tid + it * 256;
            int kk = f >> 4;
            int d4 = (f & 15) * 4;
            *(float4*)&Bs[kk][d4] = *(const float4*)(Bv + (size_t)(k0 + kk) * DK + d4);
        }
        __syncthreads();
        #pragma unroll 8
        for (int k = 0; k < 32; k++) {
            float4 a0 = *(const float4*)&As[k][ty * 4];
            ulonglong2 bu = *(const ulonglong2*)&Bs[k][tx * 4];
            float a[4] = {a0.x, a0.y, a0.z, a0.w};
            #pragma unroll
            for (int i = 0; i < 4; i++) {
                u64 ad = fpack(a[i], a[i]);
                acc[i][0] = ffma2(ad, bu.x, acc[i][0]);
                acc[i][1] = ffma2(ad, bu.y, acc[i][1]);
            }
        }
        __syncthreads();
    }

    #pragma unroll
    for (int i = 0; i < 4; i++) {
        int m = m0 + ty * 4 + i;
        float2 p0 = funpack(acc[i][0]);
        float2 p1 = funpack(acc[i][1]);
        float4 o = make_float4(p0.x, p0.y, p1.x, p1.y);
        *(float4*)(g_attn + (size_t)(b * SQ + m) * DM + h * DK + tx * 4) = o;
    }
}

// =====================================================================
// K6: g_attn[b,q,h*64+d] += sum_k probs[b,h,q,k] * relation_v[b,q,k,d]
// Round-2 layout (conflict-free stores). grid (1024, 2).
// =====================================================================
__global__ __launch_bounds__(256) void k_wrel(const float* __restrict__ relv)
{
    __shared__ __align__(16) float rvs[128][68];
    __shared__ __align__(16) float ps[NH][128];

    const int b = blockIdx.y, q = blockIdx.x;
    const int tid = threadIdx.x;
    const int d  = tid & 63;
    const int hg = tid >> 6;                   // 0..3 -> heads {hg, hg+4, hg+8}
    const float* relbase = relv + ((size_t)(b * SQ + q)) * SQ * DK;

    u64 acc2[3] = {0ull, 0ull, 0ull};

    for (int kt = 0; kt < SQ; kt += 128) {
        __syncthreads();
        #pragma unroll
        for (int it = 0; it < 8; it++) {
            int f = tid + it * 256;
            int kk = f >> 4;
            int d4 = (f & 15) * 4;
            *(float4*)&rvs[kk][d4] = *(const float4*)(relbase + (size_t)(kt + kk) * DK + d4);
        }
        #pragma unroll
        for (int it = 0; it < 2; it++) {
            int f = tid + it * 256;
            if (f < 384) {
                int hh = f >> 5;
                int k4 = (f & 31) * 4;
                *(float4*)&ps[hh][k4] =
                    *(const float4*)(g_scores + ((size_t)((b * NH + hh) * SQ + q)) * SQ + kt + k4);
            }
        }
        __syncthreads();

        #pragma unroll 4
        for (int k4 = 0; k4 < 128; k4 += 4) {
            float rv0 = rvs[k4 + 0][d];
            float rv1 = rvs[k4 + 1][d];
            float rv2 = rvs[k4 + 2][d];
            float rv3 = rvs[k4 + 3][d];
            u64 rv01 = fpack(rv0, rv1);
            u64 rv23 = fpack(rv2, rv3);
            #pragma unroll
            for (int j = 0; j < 3; j++) {
                ulonglong2 pu = *(const ulonglong2*)&ps[hg + 4 * j][k4];
                acc2[j] = ffma2(pu.x, rv01, acc2[j]);
                acc2[j] = ffma2(pu.y, rv23, acc2[j]);
            }
        }
    }

    #pragma unroll
    for (int j = 0; j < 3; j++) {
        int h = hg + 4 * j;
        float2 p = funpack(acc2[j]);
        float* dst = g_attn + (size_t)(b * SQ + q) * DM + h * DK + d;
        *dst += p.x + p.y;
    }
}

// =====================================================================
// K7: output projection. grid (16, 12).
// =====================================================================
__global__ __launch_bounds__(256) void k_out(
    const float* __restrict__ Wo, const float* __restrict__ bo, float* __restrict__ out)
{
    __shared__ __align__(16) float As[16][128];
    __shared__ __align__(16) float Bs[16][64];

    const int tid = threadIdx.x;
    const int tx = tid & 15, ty = tid >> 4;
    const int m0 = blockIdx.x * 128;
    const int n0 = blockIdx.y * 64;

    u64 acc[8][2];
    #pragma unroll
    for (int i = 0; i < 8; i++) { acc[i][0] = 0ull; acc[i][1] = 0ull; }

    for (int k0 = 0; k0 < DM; k0 += 16) {
        #pragma unroll
        for (int it = 0; it < 2; it++) {
            int f = tid + it * 256;
            int m = f >> 2;
            int kk = (f & 3) * 4;
            float4 a4 = *(const float4*)(g_attn + (size_t)(m0 + m) * DM + k0 + kk);
            As[kk + 0][m] = a4.x; As[kk + 1][m] = a4.y;
            As[kk + 2][m] = a4.z; As[kk + 3][m] = a4.w;
        }
        {
            int kk = tid >> 4;
            int nn = (tid & 15) * 4;
            *(float4*)&Bs[kk][nn] = *(const float4*)(Wo + (size_t)(k0 + kk) * DM + n0 + nn);
        }
        __syncthreads();
        #pragma unroll
        for (int k = 0; k < 16; k++) {
            float4 a0 = *(const float4*)&As[k][ty * 8];
            float4 a1 = *(const float4*)&As[k][ty * 8 + 4];
            ulonglong2 bu = *(const ulonglong2*)&Bs[k][tx * 4];
            float a[8] = {a0.x, a0.y, a0.z, a0.w, a1.x, a1.y, a1.z, a1.w};
            #pragma unroll
            for (int i = 0; i < 8; i++) {
                u64 ad = fpack(a[i], a[i]);
                acc[i][0] = ffma2(ad, bu.x, acc[i][0]);
                acc[i][1] = ffma2(ad, bu.y, acc[i][1]);
            }
        }
        __syncthreads();
    }

    float4 bb = *(const float4*)(bo + n0 + tx * 4);
    #pragma unroll
    for (int i = 0; i < 8; i++) {
        int m = m0 + ty * 8 + i;
        float2 p0 = funpack(acc[i][0]);
        float2 p1 = funpack(acc[i][1]);
        float4 o = make_float4(p0.x + bb.x, p0.y + bb.y, p1.x + bb.z, p1.y + bb.w);
        *(float4*)(out + (size_t)m * DM + n0 + tx * 4) = o;
    }
}

// =====================================================================
extern "C" void kernel_launch(void* const* d_in, const int* in_sizes, int n_in,
                              void* d_out, int out_size)
{
    const float* queries = (const float*)d_in[0];
    const float* keys    = (const float*)d_in[1];
    const float* values  = (const float*)d_in[2];
    const float* relk    = (const float*)d_in[3];
    const float* relv    = (const float*)d_in[4];
    const float* Wq = (const float*)d_in[5];
    const float* bq = (const float*)d_in[6];
    const float* Wk = (const float*)d_in[7];
    const float* bk = (const float*)d_in[8];
    const float* Wv = (const float*)d_in[9];
    const float* bv = (const float*)d_in[10];
    const float* Wo = (const float*)d_in[11];
    const float* bo = (const float*)d_in[12];
    float* out = (float*)d_out;

    static bool attr_set = false;
    if (!attr_set) {
        cudaFuncSetAttribute(k_qk, cudaFuncAttributeMaxDynamicSharedMemorySize,
                             2 * 64 * 132 * (int)sizeof(float));
        cudaFuncSetAttribute(k_qrel_sm, cudaFuncAttributeMaxDynamicSharedMemorySize,
                             (NH * SQ + 128 * 68 + NH * DK) * (int)sizeof(float));
        attr_set = true;
    }

    // K1: projections
    k_proj<<<dim3(16, 12, 3), 256>>>(queries, keys, values, Wq, Wk, Wv, bq, bk, bv);

    // K2: qk^T -> g_scores
    k_qk<<<dim3(8, 8, NB * NH), 256, 2 * 64 * 132 * sizeof(float)>>>();

    // K3: fused (+= q . relation_k) + softmax -> probs in g_scores
    k_qrel_sm<<<dim3(SQ, NB), 512,
                (NH * SQ + 128 * 68 + NH * DK) * sizeof(float)>>>(relk);

    // K5: probs @ v -> g_attn
    k_wv<<<dim3(16, NB * NH), 256>>>();

    // K6: g_attn += probs @ relation_v
    k_wrel<<<dim3(SQ, NB), 256>>>(relv);

    // K7: output projection
    k_out<<<dim3(16, 12), 256>>>(Wo, bo, out);
}

// round 5
// speedup vs baseline: 1.2109x; 1.0501x over previous
#include <cuda_runtime.h>

typedef unsigned long long u64;

#define NB 2
#define NH 12
#define SQ 1024
#define DK 64
#define DM 768

// ---------------- scratch ----------------
__device__ float g_q[NB*NH*SQ*DK];                 // pre-scaled by 1/64
__device__ float g_k[NB*NH*SQ*DK];
__device__ float g_v[NB*NH*SQ*DK];
__device__ float g_scores[(size_t)NB*NH*SQ*SQ];    // scores, then probs (in place)
__device__ float g_attn[NB*SQ*DM];

// ---------------- packed f32x2 helpers ----------------
__device__ __forceinline__ u64 fpack(float x, float y){
    u64 r; asm("mov.b64 %0,{%1,%2};" : "=l"(r) : "f"(x), "f"(y)); return r;
}
__device__ __forceinline__ u64 ffma2(u64 a, u64 b, u64 c){
    u64 d; asm("fma.rn.f32x2 %0,%1,%2,%3;" : "=l"(d) : "l"(a), "l"(b), "l"(c)); return d;
}
__device__ __forceinline__ float2 funpack(u64 v){
    float x, y; asm("mov.b64 {%0,%1},%2;" : "=f"(x), "=f"(y) : "l"(v)); return make_float2(x, y);
}

// =====================================================================
// K1: QKV projections. grid (16, 12, 3)
// =====================================================================
__global__ __launch_bounds__(256) void k_proj(
    const float* __restrict__ Xq, const float* __restrict__ Xk, const float* __restrict__ Xv,
    const float* __restrict__ Wq, const float* __restrict__ Wk, const float* __restrict__ Wv,
    const float* __restrict__ bq, const float* __restrict__ bk, const float* __restrict__ bv)
{
    const int z = blockIdx.z;
    const float* X    = (z == 0) ? Xq : (z == 1) ? Xk : Xv;
    const float* W    = (z == 0) ? Wq : (z == 1) ? Wk : Wv;
    const float* bias = (z == 0) ? bq : (z == 1) ? bk : bv;
    float* out        = (z == 0) ? g_q : (z == 1) ? g_k : g_v;
    const float scale = (z == 0) ? (1.0f / 64.0f) : 1.0f;

    __shared__ __align__(16) float As[16][128];
    __shared__ __align__(16) float Bs[16][64];

    const int tid = threadIdx.x;
    const int tx = tid & 15, ty = tid >> 4;
    const int m0 = blockIdx.x * 128;
    const int h  = blockIdx.y;
    const int n0 = h * 64;

    u64 acc[8][2];
    #pragma unroll
    for (int i = 0; i < 8; i++) { acc[i][0] = 0ull; acc[i][1] = 0ull; }

    // prefetch chunk 0
    float4 pfa[2], pfb;
    {
        #pragma unroll
        for (int it = 0; it < 2; it++) {
            int f = tid + it * 256;
            pfa[it] = *(const float4*)(X + (size_t)(m0 + (f >> 2)) * DM + (f & 3) * 4);
        }
        pfb = *(const float4*)(W + (size_t)(tid >> 4) * DM + n0 + (tid & 15) * 4);
    }

    for (int k0 = 0; k0 < DM; k0 += 16) {
        __syncthreads();
        #pragma unroll
        for (int it = 0; it < 2; it++) {
            int f = tid + it * 256;
            int m = f >> 2;
            int kk = (f & 3) * 4;
            As[kk + 0][m] = pfa[it].x; As[kk + 1][m] = pfa[it].y;
            As[kk + 2][m] = pfa[it].z; As[kk + 3][m] = pfa[it].w;
        }
        *(float4*)&Bs[tid >> 4][(tid & 15) * 4] = pfb;
        __syncthreads();

        if (k0 + 16 < DM) {
            #pragma unroll
            for (int it = 0; it < 2; it++) {
                int f = tid + it * 256;
                pfa[it] = *(const float4*)(X + (size_t)(m0 + (f >> 2)) * DM + k0 + 16 + (f & 3) * 4);
            }
            pfb = *(const float4*)(W + (size_t)(k0 + 16 + (tid >> 4)) * DM + n0 + (tid & 15) * 4);
        }

        #pragma unroll
        for (int k = 0; k < 16; k++) {
            float4 a0 = *(const float4*)&As[k][ty * 8];
            float4 a1 = *(const float4*)&As[k][ty * 8 + 4];
            ulonglong2 bu = *(const ulonglong2*)&Bs[k][tx * 4];
            float a[8] = {a0.x, a0.y, a0.z, a0.w, a1.x, a1.y, a1.z, a1.w};
            #pragma unroll
            for (int i = 0; i < 8; i++) {
                u64 ad = fpack(a[i], a[i]);
                acc[i][0] = ffma2(ad, bu.x, acc[i][0]);
                acc[i][1] = ffma2(ad, bu.y, acc[i][1]);
            }
        }
    }

    float4 bb = *(const float4*)(bias + n0 + tx * 4);
    #pragma unroll
    for (int i = 0; i < 8; i++) {
        int m = m0 + ty * 8 + i;
        int b = m >> 10;
        int s = m & (SQ - 1);
        float2 p0 = funpack(acc[i][0]);
        float2 p1 = funpack(acc[i][1]);
        float4 o;
        o.x = (p0.x + bb.x) * scale;
        o.y = (p0.y + bb.y) * scale;
        o.z = (p1.x + bb.z) * scale;
        o.w = (p1.y + bb.w) * scale;
        *(float4*)(out + ((size_t)((b * NH + h) * SQ + s)) * DK + tx * 4) = o;
    }
}

// =====================================================================
// K2: scores = q @ k^T per (b,h). grid (8, 8, 24), dyn smem 67584 B
// =====================================================================
__global__ __launch_bounds__(256) void k_qk()
{
    extern __shared__ __align__(16) float sm[];
    float (*As)[132] = (float(*)[132])sm;
    float (*Bs)[132] = (float(*)[132])(sm + 64 * 132);

    const int bh = blockIdx.z;
    const float* A  = g_q + (size_t)bh * SQ * DK;
    const float* Bm = g_k + (size_t)bh * SQ * DK;
    float* C = g_scores + (size_t)bh * SQ * SQ;

    const int m0 = blockIdx.x * 128;
    const int n0 = blockIdx.y * 128;
    const int tid = threadIdx.x;
    const int tx = tid & 15, ty = tid >> 4;

    #pragma unroll
    for (int it = 0; it < 8; it++) {
        int f = tid + it * 256;
        int m  = f >> 4;
        int d4 = (f & 15) * 4;
        float4 va = *(const float4*)(A  + (size_t)(m0 + m) * DK + d4);
        float4 vb = *(const float4*)(Bm + (size_t)(n0 + m) * DK + d4);
        As[d4 + 0][m] = va.x; As[d4 + 1][m] = va.y; As[d4 + 2][m] = va.z; As[d4 + 3][m] = va.w;
        Bs[d4 + 0][m] = vb.x; Bs[d4 + 1][m] = vb.y; Bs[d4 + 2][m] = vb.z; Bs[d4 + 3][m] = vb.w;
    }
    __syncthreads();

    u64 acc[8][4];
    #pragma unroll
    for (int i = 0; i < 8; i++)
        #pragma unroll
        for (int j = 0; j < 4; j++) acc[i][j] = 0ull;

    #pragma unroll 4
    for (int d = 0; d < 64; d++) {
        float4 a0 = *(const float4*)&As[d][ty * 8];
        float4 a1 = *(const float4*)&As[d][ty * 8 + 4];
        ulonglong2 b0 = *(const ulonglong2*)&Bs[d][tx * 8];
        ulonglong2 b1 = *(const ulonglong2*)&Bs[d][tx * 8 + 4];
        float a[8] = {a0.x, a0.y, a0.z, a0.w, a1.x, a1.y, a1.z, a1.w};
        #pragma unroll
        for (int i = 0; i < 8; i++) {
            u64 ad = fpack(a[i], a[i]);
            acc[i][0] = ffma2(ad, b0.x, acc[i][0]);
            acc[i][1] = ffma2(ad, b0.y, acc[i][1]);
            acc[i][2] = ffma2(ad, b1.x, acc[i][2]);
            acc[i][3] = ffma2(ad, b1.y, acc[i][3]);
        }
    }

    #pragma unroll
    for (int i = 0; i < 8; i++) {
        float2 p0 = funpack(acc[i][0]);
        float2 p1 = funpack(acc[i][1]);
        float2 p2 = funpack(acc[i][2]);
        float2 p3 = funpack(acc[i][3]);
        float* dst = C + (size_t)(m0 + ty * 8 + i) * SQ + n0 + tx * 8;
        *(float4*)(dst)     = make_float4(p0.x, p0.y, p1.x, p1.y);
        *(float4*)(dst + 4) = make_float4(p2.x, p2.y, p3.x, p3.y);
    }
}

// =====================================================================
// K3 (fused): per (b,q): scores += q . relation_k, then softmax -> probs.
// 512 threads, register-prefetch pipeline over relK chunks.
// grid (1024, 2), dyn smem 87040 B.
// =====================================================================
__global__ __launch_bounds__(512) void k_qrel_sm(const float* __restrict__ relk)
{
    extern __shared__ __align__(16) float sm[];
    float* ss = sm;                                        // 12288 floats
    float (*rks)[68] = (float(*)[68])(sm + NH * SQ);       // 8704 floats
    float* qs = sm + NH * SQ + 128 * 68;                   // 768 floats

    const int b = blockIdx.y, q = blockIdx.x;
    const int tid = threadIdx.x;

    // load q rows (12 heads x 64)
    if (tid < 192) {
        int hh = tid >> 4;
        int d4 = (tid & 15) * 4;
        *(float4*)&qs[hh * DK + d4] =
            *(const float4*)(g_q + ((size_t)((b * NH + hh) * SQ + q)) * DK + d4);
    }
    // load raw qk scores for all 12 heads
    #pragma unroll
    for (int it = 0; it < 6; it++) {
        int f = tid + it * 512;
        int hh = f >> 8;
        int k4 = (f & 255) * 4;
        *(float4*)&ss[hh * SQ + k4] =
            *(const float4*)(g_scores + ((size_t)((b * NH + hh) * SQ + q)) * SQ + k4);
    }

    const int klocal = tid & 127;
    const int hg = tid >> 7;                  // 0..3 -> heads [hg*3, hg*3+3)
    const float* relbase = relk + ((size_t)(b * SQ + q)) * SQ * DK;

    // prefetch chunk 0
    float4 pf[4];
    #pragma unroll
    for (int it = 0; it < 4; it++) {
        int f = tid + it * 512;
        pf[it] = *(const float4*)(relbase + (size_t)(f >> 4) * DK + (f & 15) * 4);
    }

    for (int kt = 0; kt < SQ; kt += 128) {
        __syncthreads();
        #pragma unroll
        for (int it = 0; it < 4; it++) {
            int f = tid + it * 512;
            *(float4*)&rks[f >> 4][(f & 15) * 4] = pf[it];
        }
        __syncthreads();

        if (kt + 128 < SQ) {
            #pragma unroll
            for (int it = 0; it < 4; it++) {
                int f = tid + it * 512;
                pf[it] = *(const float4*)(relbase + (size_t)(kt + 128 + (f >> 4)) * DK + (f & 15) * 4);
            }
        }

        u64 acc2[3] = {0ull, 0ull, 0ull};
        #pragma unroll
        for (int d4 = 0; d4 < 64; d4 += 4) {
            ulonglong2 r = *(const ulonglong2*)&rks[klocal][d4];
            #pragma unroll
            for (int j = 0; j < 3; j++) {
                ulonglong2 qv = *(const ulonglong2*)&qs[(hg * 3 + j) * DK + d4];
                acc2[j] = ffma2(qv.x, r.x, acc2[j]);
                acc2[j] = ffma2(qv.y, r.y, acc2[j]);
            }
        }
        #pragma unroll
        for (int j = 0; j < 3; j++) {
            float2 p = funpack(acc2[j]);
            ss[(hg * 3 + j) * SQ + kt + klocal] += p.x + p.y;
        }
    }
    __syncthreads();

    // softmax per head-row in smem, write probs to g_scores
    const int warp = tid >> 5;
    const int lane = tid & 31;
    if (warp < NH) {
        float* p = ss + warp * SQ;
        float4 v[8];
        float mx = -3.4e38f;
        #pragma unroll
        for (int j = 0; j < 8; j++) {
            v[j] = *(float4*)(p + lane * 4 + j * 128);
            mx = fmaxf(mx, fmaxf(fmaxf(v[j].x, v[j].y), fmaxf(v[j].z, v[j].w)));
        }
        #pragma unroll
        for (int o = 16; o > 0; o >>= 1) mx = fmaxf(mx, __shfl_xor_sync(0xffffffffu, mx, o));

        float s = 0.f;
        #pragma unroll
        for (int j = 0; j < 8; j++) {
            v[j].x = __expf(v[j].x - mx);
            v[j].y = __expf(v[j].y - mx);
            v[j].z = __expf(v[j].z - mx);
            v[j].w = __expf(v[j].w - mx);
            s += v[j].x + v[j].y + v[j].z + v[j].w;
        }
        #pragma unroll
        for (int o = 16; o > 0; o >>= 1) s += __shfl_xor_sync(0xffffffffu, s, o);
        const float inv = 1.0f / s;

        float* dst = g_scores + ((size_t)((b * NH + warp) * SQ + q)) * SQ;
        #pragma unroll
        for (int j = 0; j < 8; j++) {
            v[j].x *= inv; v[j].y *= inv; v[j].z *= inv; v[j].w *= inv;
            *(float4*)(dst + lane * 4 + j * 128) = v[j];
        }
    }
}

// =====================================================================
// K5: wv = probs @ v per (b,h). BM=64, BN=64, BK=32, 4x4 microtile.
// Register-prefetch pipeline. grid (16, 24). Writes g_attn.
// =====================================================================
__global__ __launch_bounds__(256) void k_wv()
{
    __shared__ __align__(16) float As[32][68];   // [k][m]
    __shared__ __align__(16) float Bs[32][68];   // [k][d]

    const int bh = blockIdx.y;
    const int b = bh / NH, h = bh % NH;
    const float* A  = g_scores + (size_t)bh * SQ * SQ;
    const float* Bv = g_v + (size_t)bh * SQ * DK;

    const int m0 = blockIdx.x * 64;
    const int tid = threadIdx.x;
    const int tx = tid & 15, ty = tid >> 4;

    u64 acc[4][2];
    #pragma unroll
    for (int i = 0; i < 4; i++) { acc[i][0] = 0ull; acc[i][1] = 0ull; }

    // prefetch chunk 0
    float4 pfa[2], pfb[2];
    #pragma unroll
    for (int it = 0; it < 2; it++) {
        int f = tid + it * 256;
        pfa[it] = *(const float4*)(A  + (size_t)(m0 + (f >> 3)) * SQ + (f & 7) * 4);
        pfb[it] = *(const float4*)(Bv + (size_t)(f >> 4) * DK + (f & 15) * 4);
    }

    for (int k0 = 0; k0 < SQ; k0 += 32) {
        __syncthreads();
        #pragma unroll
        for (int it = 0; it < 2; it++) {
            int f = tid + it * 256;
            int m  = f >> 3;
            int k4 = (f & 7) * 4;
            As[k4 + 0][m] = pfa[it].x; As[k4 + 1][m] = pfa[it].y;
            As[k4 + 2][m] = pfa[it].z; As[k4 + 3][m] = pfa[it].w;
            *(float4*)&Bs[f >> 4][(f & 15) * 4] = pfb[it];
        }
        __syncthreads();

        if (k0 + 32 < SQ) {
            #pragma unroll
            for (int it = 0; it < 2; it++) {
                int f = tid + it * 256;
                pfa[it] = *(const float4*)(A  + (size_t)(m0 + (f >> 3)) * SQ + k0 + 32 + (f & 7) * 4);
                pfb[it] = *(const float4*)(Bv + (size_t)(k0 + 32 + (f >> 4)) * DK + (f & 15) * 4);
            }
        }

        #pragma unroll 8
        for (int k = 0; k < 32; k++) {
            float4 a0 = *(const float4*)&As[k][ty * 4];
            ulonglong2 bu = *(const ulonglong2*)&Bs[k][tx * 4];
            float a[4] = {a0.x, a0.y, a0.z, a0.w};
            #pragma unroll
            for (int i = 0; i < 4; i++) {
                u64 ad = fpack(a[i], a[i]);
                acc[i][0] = ffma2(ad, bu.x, acc[i][0]);
                acc[i][1] = ffma2(ad, bu.y, acc[i][1]);
            }
        }
    }

    #pragma unroll
    for (int i = 0; i < 4; i++) {
        int m = m0 + ty * 4 + i;
        float2 p0 = funpack(acc[i][0]);
        float2 p1 = funpack(acc[i][1]);
        float4 o = make_float4(p0.x, p0.y, p1.x, p1.y);
        *(float4*)(g_attn + (size_t)(b * SQ + m) * DM + h * DK + tx * 4) = o;
    }
}

// =====================================================================
// K6: g_attn[b,q,h*64+d] += sum_k probs[b,h,q,k] * relation_v[b,q,k,d]
// Register-prefetch pipeline. grid (1024, 2).
// =====================================================================
__global__ __launch_bounds__(256) void k_wrel(const float* __restrict__ relv)
{
    __shared__ __align__(16) float rvs[128][68];
    __shared__ __align__(16) float ps[NH][128];

    const int b = blockIdx.y, q = blockIdx.x;
    const int tid = threadIdx.x;
    const int d  = tid & 63;
    const int hg = tid >> 6;                   // 0..3 -> heads {hg, hg+4, hg+8}
    const float* relbase = relv + ((size_t)(b * SQ + q)) * SQ * DK;
    const float* psrc = g_scores + ((size_t)(b * NH) * SQ + q) * SQ;

    u64 acc2[3] = {0ull, 0ull, 0ull};

    // prefetch chunk 0
    float4 pfr[8], pfp[2];
    #pragma unroll
    for (int it = 0; it < 8; it++) {
        int f = tid + it * 256;
        pfr[it] = *(const float4*)(relbase + (size_t)(f >> 4) * DK + (f & 15) * 4);
    }
    #pragma unroll
    for (int it = 0; it < 2; it++) {
        int f = tid + it * 256;
        if (f < 384)
            pfp[it] = *(const float4*)(psrc + (size_t)(f >> 5) * SQ * SQ + (f & 31) * 4);
    }

    for (int kt = 0; kt < SQ; kt += 128) {
        __syncthreads();
        #pragma unroll
        for (int it = 0; it < 8; it++) {
            int f = tid + it * 256;
            *(float4*)&rvs[f >> 4][(f & 15) * 4] = pfr[it];
        }
        #pragma unroll
        for (int it = 0; it < 2; it++) {
            int f = tid + it * 256;
            if (f < 384)
                *(float4*)&ps[f >> 5][(f & 31) * 4] = pfp[it];
        }
        __syncthreads();

        if (kt + 128 < SQ) {
            #pragma unroll
            for (int it = 0; it < 8; it++) {
                int f = tid + it * 256;
                pfr[it] = *(const float4*)(relbase + (size_t)(kt + 128 + (f >> 4)) * DK + (f & 15) * 4);
            }
            #pragma unroll
            for (int it = 0; it < 2; it++) {
                int f = tid + it * 256;
                if (f < 384)
                    pfp[it] = *(const float4*)(psrc + (size_t)(f >> 5) * SQ * SQ + kt + 128 + (f & 31) * 4);
            }
        }

        #pragma unroll 4
        for (int k4 = 0; k4 < 128; k4 += 4) {
            float rv0 = rvs[k4 + 0][d];
            float rv1 = rvs[k4 + 1][d];
            float rv2 = rvs[k4 + 2][d];
            float rv3 = rvs[k4 + 3][d];
            u64 rv01 = fpack(rv0, rv1);
            u64 rv23 = fpack(rv2, rv3);
            #pragma unroll
            for (int j = 0; j < 3; j++) {
                ulonglong2 pu = *(const ulonglong2*)&ps[hg + 4 * j][k4];
                acc2[j] = ffma2(pu.x, rv01, acc2[j]);
                acc2[j] = ffma2(pu.y, rv23, acc2[j]);
            }
        }
    }

    #pragma unroll
    for (int j = 0; j < 3; j++) {
        int h = hg + 4 * j;
        float2 p = funpack(acc2[j]);
        float* dst = g_attn + (size_t)(b * SQ + q) * DM + h * DK + d;
        *dst += p.x + p.y;
    }
}

// =====================================================================
// K7: output projection. grid (16, 12).
// =====================================================================
__global__ __launch_bounds__(256) void k_out(
    const float* __restrict__ Wo, const float* __restrict__ bo, float* __restrict__ out)
{
    __shared__ __align__(16) float As[16][128];
    __shared__ __align__(16) float Bs[16][64];

    const int tid = threadIdx.x;
    const int tx = tid & 15, ty = tid >> 4;
    const int m0 = blockIdx.x * 128;
    const int n0 = blockIdx.y * 64;

    u64 acc[8][2];
    #pragma unroll
    for (int i = 0; i < 8; i++) { acc[i][0] = 0ull; acc[i][1] = 0ull; }

    float4 pfa[2], pfb;
    #pragma unroll
    for (int it = 0; it < 2; it++) {
        int f = tid + it * 256;
        pfa[it] = *(const float4*)(g_attn + (size_t)(m0 + (f >> 2)) * DM + (f & 3) * 4);
    }
    pfb = *(const float4*)(Wo + (size_t)(tid >> 4) * DM + n0 + (tid & 15) * 4);

    for (int k0 = 0; k0 < DM; k0 += 16) {
        __syncthreads();
        #pragma unroll
        for (int it = 0; it < 2; it++) {
            int f = tid + it * 256;
            int m = f >> 2;
            int kk = (f & 3) * 4;
            As[kk + 0][m] = pfa[it].x; As[kk + 1][m] = pfa[it].y;
            As[kk + 2][m] = pfa[it].z; As[kk + 3][m] = pfa[it].w;
        }
        *(float4*)&Bs[tid >> 4][(tid & 15) * 4] = pfb;
        __syncthreads();

        if (k0 + 16 < DM) {
            #pragma unroll
            for (int it = 0; it < 2; it++) {
                int f = tid + it * 256;
                pfa[it] = *(const float4*)(g_attn + (size_t)(m0 + (f >> 2)) * DM + k0 + 16 + (f & 3) * 4);
            }
            pfb = *(const float4*)(Wo + (size_t)(k0 + 16 + (tid >> 4)) * DM + n0 + (tid & 15) * 4);
        }

        #pragma unroll
        for (int k = 0; k < 16; k++) {
            float4 a0 = *(const float4*)&As[k][ty * 8];
            float4 a1 = *(const float4*)&As[k][ty * 8 + 4];
            ulonglong2 bu = *(const ulonglong2*)&Bs[k][tx * 4];
            float a[8] = {a0.x, a0.y, a0.z, a0.w, a1.x, a1.y, a1.z, a1.w};
            #pragma unroll
            for (int i = 0; i < 8; i++) {
                u64 ad = fpack(a[i], a[i]);
                acc[i][0] = ffma2(ad, bu.x, acc[i][0]);
                acc[i][1] = ffma2(ad, bu.y, acc[i][1]);
            }
        }
    }

    float4 bb = *(const float4*)(bo + n0 + tx * 4);
    #pragma unroll
    for (int i = 0; i < 8; i++) {
        int m = m0 + ty * 8 + i;
        float2 p0 = funpack(acc[i][0]);
        float2 p1 = funpack(acc[i][1]);
        float4 o = make_float4(p0.x + bb.x, p0.y + bb.y, p1.x + bb.z, p1.y + bb.w);
        *(float4*)(out + (size_t)m * DM + n0 + tx * 4) = o;
    }
}

// =====================================================================
extern "C" void kernel_launch(void* const* d_in, const int* in_sizes, int n_in,
                              void* d_out, int out_size)
{
    const float* queries = (const float*)d_in[0];
    const float* keys    = (const float*)d_in[1];
    const float* values  = (const float*)d_in[2];
    const float* relk    = (const float*)d_in[3];
    const float* relv    = (const float*)d_in[4];
    const float* Wq = (const float*)d_in[5];
    const float* bq = (const float*)d_in[6];
    const float* Wk = (const float*)d_in[7];
    const float* bk = (const float*)d_in[8];
    const float* Wv = (const float*)d_in[9];
    const float* bv = (const float*)d_in[10];
    const float* Wo = (const float*)d_in[11];
    const float* bo = (const float*)d_in[12];
    float* out = (float*)d_out;

    static bool attr_set = false;
    if (!attr_set) {
        cudaFuncSetAttribute(k_qk, cudaFuncAttributeMaxDynamicSharedMemorySize,
                             2 * 64 * 132 * (int)sizeof(float));
        cudaFuncSetAttribute(k_qrel_sm, cudaFuncAttributeMaxDynamicSharedMemorySize,
                             (NH * SQ + 128 * 68 + NH * DK) * (int)sizeof(float));
        attr_set = true;
    }

    k_proj<<<dim3(16, 12, 3), 256>>>(queries, keys, values, Wq, Wk, Wv, bq, bk, bv);
    k_qk<<<dim3(8, 8, NB * NH), 256, 2 * 64 * 132 * sizeof(float)>>>();
    k_qrel_sm<<<dim3(SQ, NB), 512,
                (NH * SQ + 128 * 68 + NH * DK) * sizeof(float)>>>(relk);
    k_wv<<<dim3(16, NB * NH), 256>>>();
    k_wrel<<<dim3(SQ, NB), 256>>>(relv);
    k_out<<<dim3(16, 12), 256>>>(Wo, bo, out);
}

// round 6
// speedup vs baseline: 1.2795x; 1.0567x over previous
#include <cuda_runtime.h>

typedef unsigned long long u64;

#define NB 2
#define NH 12
#define SQ 1024
#define DK 64
#define DM 768

// ---------------- scratch ----------------
__device__ float g_q[NB*NH*SQ*DK];                 // pre-scaled by 1/64
__device__ float g_k[NB*NH*SQ*DK];
__device__ float g_v[NB*NH*SQ*DK];
__device__ float g_scores[(size_t)NB*NH*SQ*SQ];    // scores, then probs (in place)
__device__ float g_attn[NB*SQ*DM];                 // wv partial (k 0..511)
__device__ float g_attn2[NB*SQ*DM];                // wv partial (k 512..1023)

// ---------------- packed f32x2 helpers ----------------
__device__ __forceinline__ u64 fpack(float x, float y){
    u64 r; asm("mov.b64 %0,{%1,%2};" : "=l"(r) : "f"(x), "f"(y)); return r;
}
__device__ __forceinline__ u64 ffma2(u64 a, u64 b, u64 c){
    u64 d; asm("fma.rn.f32x2 %0,%1,%2,%3;" : "=l"(d) : "l"(a), "l"(b), "l"(c)); return d;
}
__device__ __forceinline__ float2 funpack(u64 v){
    float x, y; asm("mov.b64 {%0,%1},%2;" : "=f"(x), "=f"(y) : "l"(v)); return make_float2(x, y);
}

// =====================================================================
// K1: QKV projections. grid (16, 12, 3)
// =====================================================================
__global__ __launch_bounds__(256) void k_proj(
    const float* __restrict__ Xq, const float* __restrict__ Xk, const float* __restrict__ Xv,
    const float* __restrict__ Wq, const float* __restrict__ Wk, const float* __restrict__ Wv,
    const float* __restrict__ bq, const float* __restrict__ bk, const float* __restrict__ bv)
{
    const int z = blockIdx.z;
    const float* X    = (z == 0) ? Xq : (z == 1) ? Xk : Xv;
    const float* W    = (z == 0) ? Wq : (z == 1) ? Wk : Wv;
    const float* bias = (z == 0) ? bq : (z == 1) ? bk : bv;
    float* out        = (z == 0) ? g_q : (z == 1) ? g_k : g_v;
    const float scale = (z == 0) ? (1.0f / 64.0f) : 1.0f;

    __shared__ __align__(16) float As[16][128];
    __shared__ __align__(16) float Bs[16][64];

    const int tid = threadIdx.x;
    const int tx = tid & 15, ty = tid >> 4;
    const int m0 = blockIdx.x * 128;
    const int h  = blockIdx.y;
    const int n0 = h * 64;

    u64 acc[8][2];
    #pragma unroll
    for (int i = 0; i < 8; i++) { acc[i][0] = 0ull; acc[i][1] = 0ull; }

    float4 pfa[2], pfb;
    {
        #pragma unroll
        for (int it = 0; it < 2; it++) {
            int f = tid + it * 256;
            pfa[it] = *(const float4*)(X + (size_t)(m0 + (f >> 2)) * DM + (f & 3) * 4);
        }
        pfb = *(const float4*)(W + (size_t)(tid >> 4) * DM + n0 + (tid & 15) * 4);
    }

    for (int k0 = 0; k0 < DM; k0 += 16) {
        __syncthreads();
        #pragma unroll
        for (int it = 0; it < 2; it++) {
            int f = tid + it * 256;
            int m = f >> 2;
            int kk = (f & 3) * 4;
            As[kk + 0][m] = pfa[it].x; As[kk + 1][m] = pfa[it].y;
            As[kk + 2][m] = pfa[it].z; As[kk + 3][m] = pfa[it].w;
        }
        *(float4*)&Bs[tid >> 4][(tid & 15) * 4] = pfb;
        __syncthreads();

        if (k0 + 16 < DM) {
            #pragma unroll
            for (int it = 0; it < 2; it++) {
                int f = tid + it * 256;
                pfa[it] = *(const float4*)(X + (size_t)(m0 + (f >> 2)) * DM + k0 + 16 + (f & 3) * 4);
            }
            pfb = *(const float4*)(W + (size_t)(k0 + 16 + (tid >> 4)) * DM + n0 + (tid & 15) * 4);
        }

        #pragma unroll
        for (int k = 0; k < 16; k++) {
            float4 a0 = *(const float4*)&As[k][ty * 8];
            float4 a1 = *(const float4*)&As[k][ty * 8 + 4];
            ulonglong2 bu = *(const ulonglong2*)&Bs[k][tx * 4];
            float a[8] = {a0.x, a0.y, a0.z, a0.w, a1.x, a1.y, a1.z, a1.w};
            #pragma unroll
            for (int i = 0; i < 8; i++) {
                u64 ad = fpack(a[i], a[i]);
                acc[i][0] = ffma2(ad, bu.x, acc[i][0]);
                acc[i][1] = ffma2(ad, bu.y, acc[i][1]);
            }
        }
    }

    float4 bb = *(const float4*)(bias + n0 + tx * 4);
    #pragma unroll
    for (int i = 0; i < 8; i++) {
        int m = m0 + ty * 8 + i;
        int b = m >> 10;
        int s = m & (SQ - 1);
        float2 p0 = funpack(acc[i][0]);
        float2 p1 = funpack(acc[i][1]);
        float4 o;
        o.x = (p0.x + bb.x) * scale;
        o.y = (p0.y + bb.y) * scale;
        o.z = (p1.x + bb.z) * scale;
        o.w = (p1.y + bb.w) * scale;
        *(float4*)(out + ((size_t)((b * NH + h) * SQ + s)) * DK + tx * 4) = o;
    }
}

// =====================================================================
// K2: scores = q @ k^T per (b,h). grid (8, 8, 24), dyn smem 67584 B
// =====================================================================
__global__ __launch_bounds__(256) void k_qk()
{
    extern __shared__ __align__(16) float sm[];
    float (*As)[132] = (float(*)[132])sm;
    float (*Bs)[132] = (float(*)[132])(sm + 64 * 132);

    const int bh = blockIdx.z;
    const float* A  = g_q + (size_t)bh * SQ * DK;
    const float* Bm = g_k + (size_t)bh * SQ * DK;
    float* C = g_scores + (size_t)bh * SQ * SQ;

    const int m0 = blockIdx.x * 128;
    const int n0 = blockIdx.y * 128;
    const int tid = threadIdx.x;
    const int tx = tid & 15, ty = tid >> 4;

    #pragma unroll
    for (int it = 0; it < 8; it++) {
        int f = tid + it * 256;
        int m  = f >> 4;
        int d4 = (f & 15) * 4;
        float4 va = *(const float4*)(A  + (size_t)(m0 + m) * DK + d4);
        float4 vb = *(const float4*)(Bm + (size_t)(n0 + m) * DK + d4);
        As[d4 + 0][m] = va.x; As[d4 + 1][m] = va.y; As[d4 + 2][m] = va.z; As[d4 + 3][m] = va.w;
        Bs[d4 + 0][m] = vb.x; Bs[d4 + 1][m] = vb.y; Bs[d4 + 2][m] = vb.z; Bs[d4 + 3][m] = vb.w;
    }
    __syncthreads();

    u64 acc[8][4];
    #pragma unroll
    for (int i = 0; i < 8; i++)
        #pragma unroll
        for (int j = 0; j < 4; j++) acc[i][j] = 0ull;

    #pragma unroll 4
    for (int d = 0; d < 64; d++) {
        float4 a0 = *(const float4*)&As[d][ty * 8];
        float4 a1 = *(const float4*)&As[d][ty * 8 + 4];
        ulonglong2 b0 = *(const ulonglong2*)&Bs[d][tx * 8];
        ulonglong2 b1 = *(const ulonglong2*)&Bs[d][tx * 8 + 4];
        float a[8] = {a0.x, a0.y, a0.z, a0.w, a1.x, a1.y, a1.z, a1.w};
        #pragma unroll
        for (int i = 0; i < 8; i++) {
            u64 ad = fpack(a[i], a[i]);
            acc[i][0] = ffma2(ad, b0.x, acc[i][0]);
            acc[i][1] = ffma2(ad, b0.y, acc[i][1]);
            acc[i][2] = ffma2(ad, b1.x, acc[i][2]);
            acc[i][3] = ffma2(ad, b1.y, acc[i][3]);
        }
    }

    #pragma unroll
    for (int i = 0; i < 8; i++) {
        float2 p0 = funpack(acc[i][0]);
        float2 p1 = funpack(acc[i][1]);
        float2 p2 = funpack(acc[i][2]);
        float2 p3 = funpack(acc[i][3]);
        float* dst = C + (size_t)(m0 + ty * 8 + i) * SQ + n0 + tx * 8;
        *(float4*)(dst)     = make_float4(p0.x, p0.y, p1.x, p1.y);
        *(float4*)(dst + 4) = make_float4(p2.x, p2.y, p3.x, p3.y);
    }
}

// =====================================================================
// K3 (fused): per (b,q): scores += q . relation_k, then softmax -> probs.
// 512 threads, register-prefetch pipeline. grid (1024, 2), smem 87040 B.
// =====================================================================
__global__ __launch_bounds__(512) void k_qrel_sm(const float* __restrict__ relk)
{
    extern __shared__ __align__(16) float sm[];
    float* ss = sm;                                        // 12288 floats
    float (*rks)[68] = (float(*)[68])(sm + NH * SQ);       // 8704 floats
    float* qs = sm + NH * SQ + 128 * 68;                   // 768 floats

    const int b = blockIdx.y, q = blockIdx.x;
    const int tid = threadIdx.x;

    if (tid < 192) {
        int hh = tid >> 4;
        int d4 = (tid & 15) * 4;
        *(float4*)&qs[hh * DK + d4] =
            *(const float4*)(g_q + ((size_t)((b * NH + hh) * SQ + q)) * DK + d4);
    }
    #pragma unroll
    for (int it = 0; it < 6; it++) {
        int f = tid + it * 512;
        int hh = f >> 8;
        int k4 = (f & 255) * 4;
        *(float4*)&ss[hh * SQ + k4] =
            *(const float4*)(g_scores + ((size_t)((b * NH + hh) * SQ + q)) * SQ + k4);
    }

    const int klocal = tid & 127;
    const int hg = tid >> 7;
    const float* relbase = relk + ((size_t)(b * SQ + q)) * SQ * DK;

    float4 pf[4];
    #pragma unroll
    for (int it = 0; it < 4; it++) {
        int f = tid + it * 512;
        pf[it] = *(const float4*)(relbase + (size_t)(f >> 4) * DK + (f & 15) * 4);
    }

    for (int kt = 0; kt < SQ; kt += 128) {
        __syncthreads();
        #pragma unroll
        for (int it = 0; it < 4; it++) {
            int f = tid + it * 512;
            *(float4*)&rks[f >> 4][(f & 15) * 4] = pf[it];
        }
        __syncthreads();

        if (kt + 128 < SQ) {
            #pragma unroll
            for (int it = 0; it < 4; it++) {
                int f = tid + it * 512;
                pf[it] = *(const float4*)(relbase + (size_t)(kt + 128 + (f >> 4)) * DK + (f & 15) * 4);
            }
        }

        u64 acc2[3] = {0ull, 0ull, 0ull};
        #pragma unroll
        for (int d4 = 0; d4 < 64; d4 += 4) {
            ulonglong2 r = *(const ulonglong2*)&rks[klocal][d4];
            #pragma unroll
            for (int j = 0; j < 3; j++) {
                ulonglong2 qv = *(const ulonglong2*)&qs[(hg * 3 + j) * DK + d4];
                acc2[j] = ffma2(qv.x, r.x, acc2[j]);
                acc2[j] = ffma2(qv.y, r.y, acc2[j]);
            }
        }
        #pragma unroll
        for (int j = 0; j < 3; j++) {
            float2 p = funpack(acc2[j]);
            ss[(hg * 3 + j) * SQ + kt + klocal] += p.x + p.y;
        }
    }
    __syncthreads();

    const int warp = tid >> 5;
    const int lane = tid & 31;
    if (warp < NH) {
        float* p = ss + warp * SQ;
        float4 v[8];
        float mx = -3.4e38f;
        #pragma unroll
        for (int j = 0; j < 8; j++) {
            v[j] = *(float4*)(p + lane * 4 + j * 128);
            mx = fmaxf(mx, fmaxf(fmaxf(v[j].x, v[j].y), fmaxf(v[j].z, v[j].w)));
        }
        #pragma unroll
        for (int o = 16; o > 0; o >>= 1) mx = fmaxf(mx, __shfl_xor_sync(0xffffffffu, mx, o));

        float s = 0.f;
        #pragma unroll
        for (int j = 0; j < 8; j++) {
            v[j].x = __expf(v[j].x - mx);
            v[j].y = __expf(v[j].y - mx);
            v[j].z = __expf(v[j].z - mx);
            v[j].w = __expf(v[j].w - mx);
            s += v[j].x + v[j].y + v[j].z + v[j].w;
        }
        #pragma unroll
        for (int o = 16; o > 0; o >>= 1) s += __shfl_xor_sync(0xffffffffu, s, o);
        const float inv = 1.0f / s;

        float* dst = g_scores + ((size_t)((b * NH + warp) * SQ + q)) * SQ;
        #pragma unroll
        for (int j = 0; j < 8; j++) {
            v[j].x *= inv; v[j].y *= inv; v[j].z *= inv; v[j].w *= inv;
            *(float4*)(dst + lane * 4 + j * 128) = v[j];
        }
    }
}

// =====================================================================
// K5: wv = probs @ v per (b,h). BM=128, BN=64, BK=32, 8x8 microtile,
// 128 threads, split-K=2 (z halves -> g_attn / g_attn2). grid (8,24,2).
// =====================================================================
__global__ __launch_bounds__(128) void k_wv()
{
    __shared__ __align__(16) float As[128][36];   // [m][k], pad 36
    __shared__ __align__(16) float Bs[32][68];    // [k][d]

    const int bh = blockIdx.y;
    const int b = bh / NH, h = bh % NH;
    const int koff = blockIdx.z * 512;
    const float* A  = g_scores + (size_t)bh * SQ * SQ + koff;
    const float* Bv = g_v + ((size_t)bh * SQ + koff) * DK;
    float* outp = blockIdx.z ? g_attn2 : g_attn;

    const int m0 = blockIdx.x * 128;
    const int tid = threadIdx.x;
    const int tx = tid & 7, ty = tid >> 3;

    u64 acc[8][4];
    #pragma unroll
    for (int i = 0; i < 8; i++)
        #pragma unroll
        for (int j = 0; j < 4; j++) acc[i][j] = 0ull;

    float4 pfa[8], pfb[4];
    #pragma unroll
    for (int it = 0; it < 8; it++) {
        int f = tid + it * 128;
        pfa[it] = *(const float4*)(A + (size_t)(m0 + (f >> 3)) * SQ + (f & 7) * 4);
    }
    #pragma unroll
    for (int it = 0; it < 4; it++) {
        int f = tid + it * 128;
        pfb[it] = *(const float4*)(Bv + (size_t)(f >> 4) * DK + (f & 15) * 4);
    }

    for (int k0 = 0; k0 < 512; k0 += 32) {
        __syncthreads();
        #pragma unroll
        for (int it = 0; it < 8; it++) {
            int f = tid + it * 128;
            *(float4*)&As[f >> 3][(f & 7) * 4] = pfa[it];
        }
        #pragma unroll
        for (int it = 0; it < 4; it++) {
            int f = tid + it * 128;
            *(float4*)&Bs[f >> 4][(f & 15) * 4] = pfb[it];
        }
        __syncthreads();

        if (k0 + 32 < 512) {
            #pragma unroll
            for (int it = 0; it < 8; it++) {
                int f = tid + it * 128;
                pfa[it] = *(const float4*)(A + (size_t)(m0 + (f >> 3)) * SQ + k0 + 32 + (f & 7) * 4);
            }
            #pragma unroll
            for (int it = 0; it < 4; it++) {
                int f = tid + it * 128;
                pfb[it] = *(const float4*)(Bv + (size_t)(k0 + 32 + (f >> 4)) * DK + (f & 15) * 4);
            }
        }

        #pragma unroll 4
        for (int k = 0; k < 32; k++) {
            ulonglong2 b0 = *(const ulonglong2*)&Bs[k][tx * 8];
            ulonglong2 b1 = *(const ulonglong2*)&Bs[k][tx * 8 + 4];
            #pragma unroll
            for (int i = 0; i < 8; i++) {
                float av = As[ty * 8 + i][k];
                u64 ad = fpack(av, av);
                acc[i][0] = ffma2(ad, b0.x, acc[i][0]);
                acc[i][1] = ffma2(ad, b0.y, acc[i][1]);
                acc[i][2] = ffma2(ad, b1.x, acc[i][2]);
                acc[i][3] = ffma2(ad, b1.y, acc[i][3]);
            }
        }
    }

    #pragma unroll
    for (int i = 0; i < 8; i++) {
        int m = m0 + ty * 8 + i;
        float2 p0 = funpack(acc[i][0]);
        float2 p1 = funpack(acc[i][1]);
        float2 p2 = funpack(acc[i][2]);
        float2 p3 = funpack(acc[i][3]);
        float* dst = outp + (size_t)(b * SQ + m) * DM + h * DK + tx * 8;
        *(float4*)(dst)     = make_float4(p0.x, p0.y, p1.x, p1.y);
        *(float4*)(dst + 4) = make_float4(p2.x, p2.y, p3.x, p3.y);
    }
}

// =====================================================================
// K6: g_attn = g_attn + g_attn2 + probs @ relation_v   per (b,q).
// thread = (d-quad 16) x (head-group 4: heads hg,hg+4,hg+8) x (k-slice 4).
// Per 4-k group: 4 LDS.128 relV + 3 LDS.128 probs for 24 FFMA2.
// End: smem reduction over k-slices. grid (1024, 2).
// =====================================================================
__global__ __launch_bounds__(256) void k_wrel(const float* __restrict__ relv)
{
    __shared__ __align__(16) float rvs[128][68];   // 34816 B (reused as red)
    __shared__ __align__(16) float ps[NH][132];    // 6336 B

    const int b = blockIdx.y, q = blockIdx.x;
    const int tid = threadIdx.x;
    const int quad = tid & 15;          // d0 = quad*4
    const int hg   = (tid >> 4) & 3;    // heads hg, hg+4, hg+8
    const int ksub = tid >> 6;          // k-slice 0..3 (32 k each)
    const int d0 = quad * 4;

    const float* relbase = relv + ((size_t)(b * SQ + q)) * SQ * DK;
    const float* psrc = g_scores + ((size_t)(b * NH) * SQ + q) * SQ;

    u64 acc[3][2];
    #pragma unroll
    for (int j = 0; j < 3; j++) { acc[j][0] = 0ull; acc[j][1] = 0ull; }

    float4 pfr[8], pfp[2];
    #pragma unroll
    for (int it = 0; it < 8; it++) {
        int f = tid + it * 256;
        pfr[it] = *(const float4*)(relbase + (size_t)(f >> 4) * DK + (f & 15) * 4);
    }
    #pragma unroll
    for (int it = 0; it < 2; it++) {
        int f = tid + it * 256;
        if (f < 384)
            pfp[it] = *(const float4*)(psrc + (size_t)(f >> 5) * SQ * SQ + (f & 31) * 4);
    }

    for (int kt = 0; kt < SQ; kt += 128) {
        __syncthreads();
        #pragma unroll
        for (int it = 0; it < 8; it++) {
            int f = tid + it * 256;
            *(float4*)&rvs[f >> 4][(f & 15) * 4] = pfr[it];
        }
        #pragma unroll
        for (int it = 0; it < 2; it++) {
            int f = tid + it * 256;
            if (f < 384)
                *(float4*)&ps[f >> 5][(f & 31) * 4] = pfp[it];
        }
        __syncthreads();

        if (kt + 128 < SQ) {
            #pragma unroll
            for (int it = 0; it < 8; it++) {
                int f = tid + it * 256;
                pfr[it] = *(const float4*)(relbase + (size_t)(kt + 128 + (f >> 4)) * DK + (f & 15) * 4);
            }
            #pragma unroll
            for (int it = 0; it < 2; it++) {
                int f = tid + it * 256;
                if (f < 384)
                    pfp[it] = *(const float4*)(psrc + (size_t)(f >> 5) * SQ * SQ + kt + 128 + (f & 31) * 4);
            }
        }

        #pragma unroll
        for (int g = 0; g < 8; g++) {
            int k = ksub * 32 + g * 4;
            float4 pA = *(const float4*)&ps[hg][k];
            float4 pB = *(const float4*)&ps[hg + 4][k];
            float4 pC = *(const float4*)&ps[hg + 8][k];
            ulonglong2 rv0 = *(const ulonglong2*)&rvs[k + 0][d0];
            ulonglong2 rv1 = *(const ulonglong2*)&rvs[k + 1][d0];
            ulonglong2 rv2 = *(const ulonglong2*)&rvs[k + 2][d0];
            ulonglong2 rv3 = *(const ulonglong2*)&rvs[k + 3][d0];

            u64 s;
            s = fpack(pA.x, pA.x); acc[0][0] = ffma2(s, rv0.x, acc[0][0]); acc[0][1] = ffma2(s, rv0.y, acc[0][1]);
            s = fpack(pA.y, pA.y); acc[0][0] = ffma2(s, rv1.x, acc[0][0]); acc[0][1] = ffma2(s, rv1.y, acc[0][1]);
            s = fpack(pA.z, pA.z); acc[0][0] = ffma2(s, rv2.x, acc[0][0]); acc[0][1] = ffma2(s, rv2.y, acc[0][1]);
            s = fpack(pA.w, pA.w); acc[0][0] = ffma2(s, rv3.x, acc[0][0]); acc[0][1] = ffma2(s, rv3.y, acc[0][1]);

            s = fpack(pB.x, pB.x); acc[1][0] = ffma2(s, rv0.x, acc[1][0]); acc[1][1] = ffma2(s, rv0.y, acc[1][1]);
            s = fpack(pB.y, pB.y); acc[1][0] = ffma2(s, rv1.x, acc[1][0]); acc[1][1] = ffma2(s, rv1.y, acc[1][1]);
            s = fpack(pB.z, pB.z); acc[1][0] = ffma2(s, rv2.x, acc[1][0]); acc[1][1] = ffma2(s, rv2.y, acc[1][1]);
            s = fpack(pB.w, pB.w); acc[1][0] = ffma2(s, rv3.x, acc[1][0]); acc[1][1] = ffma2(s, rv3.y, acc[1][1]);

            s = fpack(pC.x, pC.x); acc[2][0] = ffma2(s, rv0.x, acc[2][0]); acc[2][1] = ffma2(s, rv0.y, acc[2][1]);
            s = fpack(pC.y, pC.y); acc[2][0] = ffma2(s, rv1.x, acc[2][0]); acc[2][1] = ffma2(s, rv1.y, acc[2][1]);
            s = fpack(pC.z, pC.z); acc[2][0] = ffma2(s, rv2.x, acc[2][0]); acc[2][1] = ffma2(s, rv2.y, acc[2][1]);
            s = fpack(pC.w, pC.w); acc[2][0] = ffma2(s, rv3.x, acc[2][0]); acc[2][1] = ffma2(s, rv3.y, acc[2][1]);
        }
    }

    // ---- reduce over the 4 k-slices (alias red onto rvs) ----
    __syncthreads();
    float* red = &rvs[0][0];   // 256 threads x 12 floats = 12288 B
    #pragma unroll
    for (int j = 0; j < 3; j++) {
        float2 lo = funpack(acc[j][0]);
        float2 hi = funpack(acc[j][1]);
        red[tid * 12 + j * 4 + 0] = lo.x;
        red[tid * 12 + j * 4 + 1] = lo.y;
        red[tid * 12 + j * 4 + 2] = hi.x;
        red[tid * 12 + j * 4 + 3] = hi.y;
    }
    __syncthreads();

    if (tid < 64) {
        const int quad_ = tid & 15;
        const int hg_   = tid >> 4;
        #pragma unroll
        for (int j = 0; j < 3; j++) {
            int hh = hg_ + 4 * j;
            float4 sum = make_float4(0.f, 0.f, 0.f, 0.f);
            #pragma unroll
            for (int s4 = 0; s4 < 4; s4++) {
                const float* r = red + (size_t)(tid + 64 * s4) * 12 + j * 4;
                sum.x += r[0]; sum.y += r[1]; sum.z += r[2]; sum.w += r[3];
            }
            size_t idx = (size_t)(b * SQ + q) * DM + hh * DK + quad_ * 4;
            float4 a1 = *(const float4*)(g_attn + idx);
            float4 a2 = *(const float4*)(g_attn2 + idx);
            sum.x += a1.x + a2.x; sum.y += a1.y + a2.y;
            sum.z += a1.z + a2.z; sum.w += a1.w + a2.w;
            *(float4*)(g_attn + idx) = sum;
        }
    }
}

// =====================================================================
// K7: output projection. grid (16, 12).
// =====================================================================
__global__ __launch_bounds__(256) void k_out(
    const float* __restrict__ Wo, const float* __restrict__ bo, float* __restrict__ out)
{
    __shared__ __align__(16) float As[16][128];
    __shared__ __align__(16) float Bs[16][64];

    const int tid = threadIdx.x;
    const int tx = tid & 15, ty = tid >> 4;
    const int m0 = blockIdx.x * 128;
    const int n0 = blockIdx.y * 64;

    u64 acc[8][2];
    #pragma unroll
    for (int i = 0; i < 8; i++) { acc[i][0] = 0ull; acc[i][1] = 0ull; }

    float4 pfa[2], pfb;
    #pragma unroll
    for (int it = 0; it < 2; it++) {
        int f = tid + it * 256;
        pfa[it] = *(const float4*)(g_attn + (size_t)(m0 + (f >> 2)) * DM + (f & 3) * 4);
    }
    pfb = *(const float4*)(Wo + (size_t)(tid >> 4) * DM + n0 + (tid & 15) * 4);

    for (int k0 = 0; k0 < DM; k0 += 16) {
        __syncthreads();
        #pragma unroll
        for (int it = 0; it < 2; it++) {
            int f = tid + it * 256;
            int m = f >> 2;
            int kk = (f & 3) * 4;
            As[kk + 0][m] = pfa[it].x; As[kk + 1][m] = pfa[it].y;
            As[kk + 2][m] = pfa[it].z; As[kk + 3][m] = pfa[it].w;
        }
        *(float4*)&Bs[tid >> 4][(tid & 15) * 4] = pfb;
        __syncthreads();

        if (k0 + 16 < DM) {
            #pragma unroll
            for (int it = 0; it < 2; it++) {
                int f = tid + it * 256;
                pfa[it] = *(const float4*)(g_attn + (size_t)(m0 + (f >> 2)) * DM + k0 + 16 + (f & 3) * 4);
            }
            pfb = *(const float4*)(Wo + (size_t)(k0 + 16 + (tid >> 4)) * DM + n0 + (tid & 15) * 4);
        }

        #pragma unroll
        for (int k = 0; k < 16; k++) {
            float4 a0 = *(const float4*)&As[k][ty * 8];
            float4 a1 = *(const float4*)&As[k][ty * 8 + 4];
            ulonglong2 bu = *(const ulonglong2*)&Bs[k][tx * 4];
            float a[8] = {a0.x, a0.y, a0.z, a0.w, a1.x, a1.y, a1.z, a1.w};
            #pragma unroll
            for (int i = 0; i < 8; i++) {
                u64 ad = fpack(a[i], a[i]);
                acc[i][0] = ffma2(ad, bu.x, acc[i][0]);
                acc[i][1] = ffma2(ad, bu.y, acc[i][1]);
            }
        }
    }

    float4 bb = *(const float4*)(bo + n0 + tx * 4);
    #pragma unroll
    for (int i = 0; i < 8; i++) {
        int m = m0 + ty * 8 + i;
        float2 p0 = funpack(acc[i][0]);
        float2 p1 = funpack(acc[i][1]);
        float4 o = make_float4(p0.x + bb.x, p0.y + bb.y, p1.x + bb.z, p1.y + bb.w);
        *(float4*)(out + (size_t)m * DM + n0 + tx * 4) = o;
    }
}

// =====================================================================
extern "C" void kernel_launch(void* const* d_in, const int* in_sizes, int n_in,
                              void* d_out, int out_size)
{
    const float* queries = (const float*)d_in[0];
    const float* keys    = (const float*)d_in[1];
    const float* values  = (const float*)d_in[2];
    const float* relk    = (const float*)d_in[3];
    const float* relv    = (const float*)d_in[4];
    const float* Wq = (const float*)d_in[5];
    const float* bq = (const float*)d_in[6];
    const float* Wk = (const float*)d_in[7];
    const float* bk = (const float*)d_in[8];
    const float* Wv = (const float*)d_in[9];
    const float* bv = (const float*)d_in[10];
    const float* Wo = (const float*)d_in[11];
    const float* bo = (const float*)d_in[12];
    float* out = (float*)d_out;

    static bool attr_set = false;
    if (!attr_set) {
        cudaFuncSetAttribute(k_qk, cudaFuncAttributeMaxDynamicSharedMemorySize,
                             2 * 64 * 132 * (int)sizeof(float));
        cudaFuncSetAttribute(k_qrel_sm, cudaFuncAttributeMaxDynamicSharedMemorySize,
                             (NH * SQ + 128 * 68 + NH * DK) * (int)sizeof(float));
        attr_set = true;
    }

    k_proj<<<dim3(16, 12, 3), 256>>>(queries, keys, values, Wq, Wk, Wv, bq, bk, bv);
    k_qk<<<dim3(8, 8, NB * NH), 256, 2 * 64 * 132 * sizeof(float)>>>();
    k_qrel_sm<<<dim3(SQ, NB), 512,
                (NH * SQ + 128 * 68 + NH * DK) * sizeof(float)>>>(relk);
    k_wv<<<dim3(8, NB * NH, 2), 128>>>();
    k_wrel<<<dim3(SQ, NB), 256>>>(relv);
    k_out<<<dim3(16, 12), 256>>>(Wo, bo, out);
}

// round 7
// speedup vs baseline: 1.4904x; 1.1649x over previous
#include <cuda_runtime.h>

typedef unsigned long long u64;
typedef unsigned int u32;

#define NB 2
#define NH 12
#define SQ 1024
#define DK 64
#define DM 768

// ---------------- scratch ----------------
__device__ float g_q[NB*NH*SQ*DK];                 // pre-scaled by 1/64
__device__ float g_k[NB*NH*SQ*DK];
__device__ float g_v[NB*NH*SQ*DK];
__device__ float g_scores[(size_t)NB*NH*SQ*SQ];    // scores, then probs (in place)
__device__ float g_attn[NB*SQ*DM];                 // wv partial (k 0..511)
__device__ float g_attn2[NB*SQ*DM];                // wv partial (k 512..1023)

// ---------------- packed f32x2 helpers ----------------
__device__ __forceinline__ u64 fpack(float x, float y){
    u64 r; asm("mov.b64 %0,{%1,%2};" : "=l"(r) : "f"(x), "f"(y)); return r;
}
__device__ __forceinline__ u64 ffma2(u64 a, u64 b, u64 c){
    u64 d; asm("fma.rn.f32x2 %0,%1,%2,%3;" : "=l"(d) : "l"(a), "l"(b), "l"(c)); return d;
}
__device__ __forceinline__ float2 funpack(u64 v){
    float x, y; asm("mov.b64 {%0,%1},%2;" : "=f"(x), "=f"(y) : "l"(v)); return make_float2(x, y);
}

// ---------------- tf32 mma helpers ----------------
__device__ __forceinline__ u32 to_tf32(float f){
    u32 u; asm("cvt.rna.tf32.f32 %0, %1;" : "=r"(u) : "f"(f)); return u;
}
__device__ __forceinline__ uint4 cvt4(float4 v){
    uint4 u; u.x = to_tf32(v.x); u.y = to_tf32(v.y); u.z = to_tf32(v.z); u.w = to_tf32(v.w);
    return u;
}
__device__ __forceinline__ void mma_tf32(float* c, const u32* a, const u32* b){
    asm volatile(
        "mma.sync.aligned.m16n8k8.row.col.f32.tf32.tf32.f32 "
        "{%0,%1,%2,%3}, {%4,%5,%6,%7}, {%8,%9}, {%0,%1,%2,%3};"
        : "+f"(c[0]), "+f"(c[1]), "+f"(c[2]), "+f"(c[3])
        : "r"(a[0]), "r"(a[1]), "r"(a[2]), "r"(a[3]), "r"(b[0]), "r"(b[1]));
}

// =====================================================================
// K1: QKV projections. grid (16, 12, 3)
// =====================================================================
__global__ __launch_bounds__(256) void k_proj(
    const float* __restrict__ Xq, const float* __restrict__ Xk, const float* __restrict__ Xv,
    const float* __restrict__ Wq, const float* __restrict__ Wk, const float* __restrict__ Wv,
    const float* __restrict__ bq, const float* __restrict__ bk, const float* __restrict__ bv)
{
    const int z = blockIdx.z;
    const float* X    = (z == 0) ? Xq : (z == 1) ? Xk : Xv;
    const float* W    = (z == 0) ? Wq : (z == 1) ? Wk : Wv;
    const float* bias = (z == 0) ? bq : (z == 1) ? bk : bv;
    float* out        = (z == 0) ? g_q : (z == 1) ? g_k : g_v;
    const float scale = (z == 0) ? (1.0f / 64.0f) : 1.0f;

    __shared__ __align__(16) float As[16][128];
    __shared__ __align__(16) float Bs[16][64];

    const int tid = threadIdx.x;
    const int tx = tid & 15, ty = tid >> 4;
    const int m0 = blockIdx.x * 128;
    const int h  = blockIdx.y;
    const int n0 = h * 64;

    u64 acc[8][2];
    #pragma unroll
    for (int i = 0; i < 8; i++) { acc[i][0] = 0ull; acc[i][1] = 0ull; }

    float4 pfa[2], pfb;
    {
        #pragma unroll
        for (int it = 0; it < 2; it++) {
            int f = tid + it * 256;
            pfa[it] = *(const float4*)(X + (size_t)(m0 + (f >> 2)) * DM + (f & 3) * 4);
        }
        pfb = *(const float4*)(W + (size_t)(tid >> 4) * DM + n0 + (tid & 15) * 4);
    }

    for (int k0 = 0; k0 < DM; k0 += 16) {
        __syncthreads();
        #pragma unroll
        for (int it = 0; it < 2; it++) {
            int f = tid + it * 256;
            int m = f >> 2;
            int kk = (f & 3) * 4;
            As[kk + 0][m] = pfa[it].x; As[kk + 1][m] = pfa[it].y;
            As[kk + 2][m] = pfa[it].z; As[kk + 3][m] = pfa[it].w;
        }
        *(float4*)&Bs[tid >> 4][(tid & 15) * 4] = pfb;
        __syncthreads();

        if (k0 + 16 < DM) {
            #pragma unroll
            for (int it = 0; it < 2; it++) {
                int f = tid + it * 256;
                pfa[it] = *(const float4*)(X + (size_t)(m0 + (f >> 2)) * DM + k0 + 16 + (f & 3) * 4);
            }
            pfb = *(const float4*)(W + (size_t)(k0 + 16 + (tid >> 4)) * DM + n0 + (tid & 15) * 4);
        }

        #pragma unroll
        for (int k = 0; k < 16; k++) {
            float4 a0 = *(const float4*)&As[k][ty * 8];
            float4 a1 = *(const float4*)&As[k][ty * 8 + 4];
            ulonglong2 bu = *(const ulonglong2*)&Bs[k][tx * 4];
            float a[8] = {a0.x, a0.y, a0.z, a0.w, a1.x, a1.y, a1.z, a1.w};
            #pragma unroll
            for (int i = 0; i < 8; i++) {
                u64 ad = fpack(a[i], a[i]);
                acc[i][0] = ffma2(ad, bu.x, acc[i][0]);
                acc[i][1] = ffma2(ad, bu.y, acc[i][1]);
            }
        }
    }

    float4 bb = *(const float4*)(bias + n0 + tx * 4);
    #pragma unroll
    for (int i = 0; i < 8; i++) {
        int m = m0 + ty * 8 + i;
        int b = m >> 10;
        int s = m & (SQ - 1);
        float2 p0 = funpack(acc[i][0]);
        float2 p1 = funpack(acc[i][1]);
        float4 o;
        o.x = (p0.x + bb.x) * scale;
        o.y = (p0.y + bb.y) * scale;
        o.z = (p1.x + bb.z) * scale;
        o.w = (p1.y + bb.w) * scale;
        *(float4*)(out + ((size_t)((b * NH + h) * SQ + s)) * DK + tx * 4) = o;
    }
}

// =====================================================================
// K2: scores = q @ k^T per (b,h) via tf32 mma. CTA tile 128x128.
// 256 threads, warp grid 2(m)x4(n), warp tile 64x32.
// grid (8, 8, 24), dyn smem 69632 B.
// =====================================================================
__global__ __launch_bounds__(256) void k_qk()
{
    extern __shared__ __align__(16) u32 smu[];
    u32 (*Qs)[68] = (u32(*)[68])smu;              // [128][68] tf32
    u32 (*Ks)[68] = (u32(*)[68])(smu + 128 * 68); // [128][68] tf32

    const int bh = blockIdx.z;
    const float* Aq = g_q + (size_t)bh * SQ * DK;
    const float* Bk = g_k + (size_t)bh * SQ * DK;
    float* C = g_scores + (size_t)bh * SQ * SQ;

    const int m0 = blockIdx.x * 128;
    const int n0 = blockIdx.y * 128;
    const int tid = threadIdx.x;
    const int lane = tid & 31;
    const int warp = tid >> 5;
    const int wm = warp >> 2;        // 0..1 -> m offset *64
    const int wn = warp & 3;         // 0..3 -> n offset *32
    const int rq = lane >> 2;        // 0..7
    const int cq = lane & 3;         // 0..3

    // load q,k tiles (128x64 each) converting to tf32
    #pragma unroll
    for (int it = 0; it < 8; it++) {
        int f = tid + it * 256;
        int r  = f >> 4;
        int d4 = (f & 15) * 4;
        float4 va = *(const float4*)(Aq + (size_t)(m0 + r) * DK + d4);
        float4 vb = *(const float4*)(Bk + (size_t)(n0 + r) * DK + d4);
        *(uint4*)&Qs[r][d4] = cvt4(va);
        *(uint4*)&Ks[r][d4] = cvt4(vb);
    }
    __syncthreads();

    float acc[4][4][4];
    #pragma unroll
    for (int i = 0; i < 4; i++)
        #pragma unroll
        for (int j = 0; j < 4; j++)
            #pragma unroll
            for (int t = 0; t < 4; t++) acc[i][j][t] = 0.f;

    #pragma unroll
    for (int ks = 0; ks < 8; ks++) {
        int d0 = ks * 8;
        u32 a[4][4], bf[4][2];
        #pragma unroll
        for (int mi = 0; mi < 4; mi++) {
            int r = wm * 64 + mi * 16 + rq;
            a[mi][0] = Qs[r][d0 + cq];
            a[mi][1] = Qs[r + 8][d0 + cq];
            a[mi][2] = Qs[r][d0 + cq + 4];
            a[mi][3] = Qs[r + 8][d0 + cq + 4];
        }
        #pragma unroll
        for (int ni = 0; ni < 4; ni++) {
            int n = wn * 32 + ni * 8 + rq;
            bf[ni][0] = Ks[n][d0 + cq];
            bf[ni][1] = Ks[n][d0 + cq + 4];
        }
        #pragma unroll
        for (int mi = 0; mi < 4; mi++)
            #pragma unroll
            for (int ni = 0; ni < 4; ni++)
                mma_tf32(acc[mi][ni], a[mi], bf[ni]);
    }

    #pragma unroll
    for (int mi = 0; mi < 4; mi++) {
        #pragma unroll
        for (int ni = 0; ni < 4; ni++) {
            int r0 = m0 + wm * 64 + mi * 16 + rq;
            int c0 = n0 + wn * 32 + ni * 8 + cq * 2;
            *(float2*)(C + (size_t)r0 * SQ + c0)       = make_float2(acc[mi][ni][0], acc[mi][ni][1]);
            *(float2*)(C + (size_t)(r0 + 8) * SQ + c0) = make_float2(acc[mi][ni][2], acc[mi][ni][3]);
        }
    }
}

// =====================================================================
// K3 (fused): per (b,q): scores += q . relation_k, then softmax -> probs.
// 512 threads, register-prefetch pipeline. grid (1024, 2), smem 87040 B.
// =====================================================================
__global__ __launch_bounds__(512) void k_qrel_sm(const float* __restrict__ relk)
{
    extern __shared__ __align__(16) float sm[];
    float* ss = sm;                                        // 12288 floats
    float (*rks)[68] = (float(*)[68])(sm + NH * SQ);       // 8704 floats
    float* qs = sm + NH * SQ + 128 * 68;                   // 768 floats

    const int b = blockIdx.y, q = blockIdx.x;
    const int tid = threadIdx.x;

    if (tid < 192) {
        int hh = tid >> 4;
        int d4 = (tid & 15) * 4;
        *(float4*)&qs[hh * DK + d4] =
            *(const float4*)(g_q + ((size_t)((b * NH + hh) * SQ + q)) * DK + d4);
    }
    #pragma unroll
    for (int it = 0; it < 6; it++) {
        int f = tid + it * 512;
        int hh = f >> 8;
        int k4 = (f & 255) * 4;
        *(float4*)&ss[hh * SQ + k4] =
            *(const float4*)(g_scores + ((size_t)((b * NH + hh) * SQ + q)) * SQ + k4);
    }

    const int klocal = tid & 127;
    const int hg = tid >> 7;
    const float* relbase = relk + ((size_t)(b * SQ + q)) * SQ * DK;

    float4 pf[4];
    #pragma unroll
    for (int it = 0; it < 4; it++) {
        int f = tid + it * 512;
        pf[it] = *(const float4*)(relbase + (size_t)(f >> 4) * DK + (f & 15) * 4);
    }

    for (int kt = 0; kt < SQ; kt += 128) {
        __syncthreads();
        #pragma unroll
        for (int it = 0; it < 4; it++) {
            int f = tid + it * 512;
            *(float4*)&rks[f >> 4][(f & 15) * 4] = pf[it];
        }
        __syncthreads();

        if (kt + 128 < SQ) {
            #pragma unroll
            for (int it = 0; it < 4; it++) {
                int f = tid + it * 512;
                pf[it] = *(const float4*)(relbase + (size_t)(kt + 128 + (f >> 4)) * DK + (f & 15) * 4);
            }
        }

        u64 acc2[3] = {0ull, 0ull, 0ull};
        #pragma unroll
        for (int d4 = 0; d4 < 64; d4 += 4) {
            ulonglong2 r = *(const ulonglong2*)&rks[klocal][d4];
            #pragma unroll
            for (int j = 0; j < 3; j++) {
                ulonglong2 qv = *(const ulonglong2*)&qs[(hg * 3 + j) * DK + d4];
                acc2[j] = ffma2(qv.x, r.x, acc2[j]);
                acc2[j] = ffma2(qv.y, r.y, acc2[j]);
            }
        }
        #pragma unroll
        for (int j = 0; j < 3; j++) {
            float2 p = funpack(acc2[j]);
            ss[(hg * 3 + j) * SQ + kt + klocal] += p.x + p.y;
        }
    }
    __syncthreads();

    const int warp = tid >> 5;
    const int lane = tid & 31;
    if (warp < NH) {
        float* p = ss + warp * SQ;
        float4 v[8];
        float mx = -3.4e38f;
        #pragma unroll
        for (int j = 0; j < 8; j++) {
            v[j] = *(float4*)(p + lane * 4 + j * 128);
            mx = fmaxf(mx, fmaxf(fmaxf(v[j].x, v[j].y), fmaxf(v[j].z, v[j].w)));
        }
        #pragma unroll
        for (int o = 16; o > 0; o >>= 1) mx = fmaxf(mx, __shfl_xor_sync(0xffffffffu, mx, o));

        float s = 0.f;
        #pragma unroll
        for (int j = 0; j < 8; j++) {
            v[j].x = __expf(v[j].x - mx);
            v[j].y = __expf(v[j].y - mx);
            v[j].z = __expf(v[j].z - mx);
            v[j].w = __expf(v[j].w - mx);
            s += v[j].x + v[j].y + v[j].z + v[j].w;
        }
        #pragma unroll
        for (int o = 16; o > 0; o >>= 1) s += __shfl_xor_sync(0xffffffffu, s, o);
        const float inv = 1.0f / s;

        float* dst = g_scores + ((size_t)((b * NH + warp) * SQ + q)) * SQ;
        #pragma unroll
        for (int j = 0; j < 8; j++) {
            v[j].x *= inv; v[j].y *= inv; v[j].z *= inv; v[j].w *= inv;
            *(float4*)(dst + lane * 4 + j * 128) = v[j];
        }
    }
}

// =====================================================================
// K5: wv = probs @ v per (b,h) via tf32 mma. BM=128, BN=64, BK=32.
// 256 threads, warp grid 4(m)x2(n), warp tile 32x32. split-K=2.
// grid (8, 24, 2).
// =====================================================================
__global__ __launch_bounds__(256) void k_wv()
{
    __shared__ __align__(16) u32 As[128][36];  // probs tf32 [m][k]
    __shared__ __align__(16) u32 Bs[32][72];   // v tf32 [k][n]

    const int bh = blockIdx.y;
    const int b = bh / NH, h = bh % NH;
    const int koff = blockIdx.z * 512;
    const float* A  = g_scores + (size_t)bh * SQ * SQ + koff;
    const float* Bv = g_v + ((size_t)bh * SQ + koff) * DK;
    float* outp = blockIdx.z ? g_attn2 : g_attn;

    const int m0 = blockIdx.x * 128;
    const int tid = threadIdx.x;
    const int lane = tid & 31;
    const int warp = tid >> 5;
    const int wm = warp >> 1;    // 0..3 -> m offset *32
    const int wn = warp & 1;     // 0..1 -> n offset *32
    const int rq = lane >> 2;
    const int cq = lane & 3;

    float acc[2][4][4];
    #pragma unroll
    for (int i = 0; i < 2; i++)
        #pragma unroll
        for (int j = 0; j < 4; j++)
            #pragma unroll
            for (int t = 0; t < 4; t++) acc[i][j][t] = 0.f;

    float4 pfa[4], pfb[2];
    #pragma unroll
    for (int it = 0; it < 4; it++) {
        int f = tid + it * 256;
        pfa[it] = *(const float4*)(A + (size_t)(m0 + (f >> 3)) * SQ + (f & 7) * 4);
    }
    #pragma unroll
    for (int it = 0; it < 2; it++) {
        int f = tid + it * 256;
        pfb[it] = *(const float4*)(Bv + (size_t)(f >> 4) * DK + (f & 15) * 4);
    }

    for (int k0 = 0; k0 < 512; k0 += 32) {
        __syncthreads();
        #pragma unroll
        for (int it = 0; it < 4; it++) {
            int f = tid + it * 256;
            *(uint4*)&As[f >> 3][(f & 7) * 4] = cvt4(pfa[it]);
        }
        #pragma unroll
        for (int it = 0; it < 2; it++) {
            int f = tid + it * 256;
            *(uint4*)&Bs[f >> 4][(f & 15) * 4] = cvt4(pfb[it]);
        }
        __syncthreads();

        if (k0 + 32 < 512) {
            #pragma unroll
            for (int it = 0; it < 4; it++) {
                int f = tid + it * 256;
                pfa[it] = *(const float4*)(A + (size_t)(m0 + (f >> 3)) * SQ + k0 + 32 + (f & 7) * 4);
            }
            #pragma unroll
            for (int it = 0; it < 2; it++) {
                int f = tid + it * 256;
                pfb[it] = *(const float4*)(Bv + (size_t)(k0 + 32 + (f >> 4)) * DK + (f & 15) * 4);
            }
        }

        #pragma unroll
        for (int ks = 0; ks < 4; ks++) {
            int kk = ks * 8;
            u32 a[2][4], bf[4][2];
            #pragma unroll
            for (int mi = 0; mi < 2; mi++) {
                int r = wm * 32 + mi * 16 + rq;
                a[mi][0] = As[r][kk + cq];
                a[mi][1] = As[r + 8][kk + cq];
                a[mi][2] = As[r][kk + cq + 4];
                a[mi][3] = As[r + 8][kk + cq + 4];
            }
            #pragma unroll
            for (int ni = 0; ni < 4; ni++) {
                int n = wn * 32 + ni * 8 + rq;
                bf[ni][0] = Bs[kk + cq][n];
                bf[ni][1] = Bs[kk + cq + 4][n];
            }
            #pragma unroll
            for (int mi = 0; mi < 2; mi++)
                #pragma unroll
                for (int ni = 0; ni < 4; ni++)
                    mma_tf32(acc[mi][ni], a[mi], bf[ni]);
        }
    }

    #pragma unroll
    for (int mi = 0; mi < 2; mi++) {
        #pragma unroll
        for (int ni = 0; ni < 4; ni++) {
            int r0 = m0 + wm * 32 + mi * 16 + rq;
            int c0 = wn * 32 + ni * 8 + cq * 2;
            float* dst0 = outp + (size_t)(b * SQ + r0) * DM + h * DK + c0;
            float* dst1 = outp + (size_t)(b * SQ + r0 + 8) * DM + h * DK + c0;
            *(float2*)dst0 = make_float2(acc[mi][ni][0], acc[mi][ni][1]);
            *(float2*)dst1 = make_float2(acc[mi][ni][2], acc[mi][ni][3]);
        }
    }
}

// =====================================================================
// K6: g_attn = g_attn + g_attn2 + probs @ relation_v   per (b,q).
// grid (1024, 2).
// =====================================================================
__global__ __launch_bounds__(256) void k_wrel(const float* __restrict__ relv)
{
    __shared__ __align__(16) float rvs[128][68];   // reused as red
    __shared__ __align__(16) float ps[NH][132];

    const int b = blockIdx.y, q = blockIdx.x;
    const int tid = threadIdx.x;
    const int quad = tid & 15;
    const int hg   = (tid >> 4) & 3;
    const int ksub = tid >> 6;
    const int d0 = quad * 4;

    const float* relbase = relv + ((size_t)(b * SQ + q)) * SQ * DK;
    const float* psrc = g_scores + ((size_t)(b * NH) * SQ + q) * SQ;

    u64 acc[3][2];
    #pragma unroll
    for (int j = 0; j < 3; j++) { acc[j][0] = 0ull; acc[j][1] = 0ull; }

    float4 pfr[8], pfp[2];
    #pragma unroll
    for (int it = 0; it < 8; it++) {
        int f = tid + it * 256;
        pfr[it] = *(const float4*)(relbase + (size_t)(f >> 4) * DK + (f & 15) * 4);
    }
    #pragma unroll
    for (int it = 0; it < 2; it++) {
        int f = tid + it * 256;
        if (f < 384)
            pfp[it] = *(const float4*)(psrc + (size_t)(f >> 5) * SQ * SQ + (f & 31) * 4);
    }

    for (int kt = 0; kt < SQ; kt += 128) {
        __syncthreads();
        #pragma unroll
        for (int it = 0; it < 8; it++) {
            int f = tid + it * 256;
            *(float4*)&rvs[f >> 4][(f & 15) * 4] = pfr[it];
        }
        #pragma unroll
        for (int it = 0; it < 2; it++) {
            int f = tid + it * 256;
            if (f < 384)
                *(float4*)&ps[f >> 5][(f & 31) * 4] = pfp[it];
        }
        __syncthreads();

        if (kt + 128 < SQ) {
            #pragma unroll
            for (int it = 0; it < 8; it++) {
                int f = tid + it * 256;
                pfr[it] = *(const float4*)(relbase + (size_t)(kt + 128 + (f >> 4)) * DK + (f & 15) * 4);
            }
            #pragma unroll
            for (int it = 0; it < 2; it++) {
                int f = tid + it * 256;
                if (f < 384)
                    pfp[it] = *(const float4*)(psrc + (size_t)(f >> 5) * SQ * SQ + kt + 128 + (f & 31) * 4);
            }
        }

        #pragma unroll
        for (int g = 0; g < 8; g++) {
            int k = ksub * 32 + g * 4;
            float4 pA = *(const float4*)&ps[hg][k];
            float4 pB = *(const float4*)&ps[hg + 4][k];
            float4 pC = *(const float4*)&ps[hg + 8][k];
            ulonglong2 rv0 = *(const ulonglong2*)&rvs[k + 0][d0];
            ulonglong2 rv1 = *(const ulonglong2*)&rvs[k + 1][d0];
            ulonglong2 rv2 = *(const ulonglong2*)&rvs[k + 2][d0];
            ulonglong2 rv3 = *(const ulonglong2*)&rvs[k + 3][d0];

            u64 s;
            s = fpack(pA.x, pA.x); acc[0][0] = ffma2(s, rv0.x, acc[0][0]); acc[0][1] = ffma2(s, rv0.y, acc[0][1]);
            s = fpack(pA.y, pA.y); acc[0][0] = ffma2(s, rv1.x, acc[0][0]); acc[0][1] = ffma2(s, rv1.y, acc[0][1]);
            s = fpack(pA.z, pA.z); acc[0][0] = ffma2(s, rv2.x, acc[0][0]); acc[0][1] = ffma2(s, rv2.y, acc[0][1]);
            s = fpack(pA.w, pA.w); acc[0][0] = ffma2(s, rv3.x, acc[0][0]); acc[0][1] = ffma2(s, rv3.y, acc[0][1]);

            s = fpack(pB.x, pB.x); acc[1][0] = ffma2(s, rv0.x, acc[1][0]); acc[1][1] = ffma2(s, rv0.y, acc[1][1]);
            s = fpack(pB.y, pB.y); acc[1][0] = ffma2(s, rv1.x, acc[1][0]); acc[1][1] = ffma2(s, rv1.y, acc[1][1]);
            s = fpack(pB.z, pB.z); acc[1][0] = ffma2(s, rv2.x, acc[1][0]); acc[1][1] = ffma2(s, rv2.y, acc[1][1]);
            s = fpack(pB.w, pB.w); acc[1][0] = ffma2(s, rv3.x, acc[1][0]); acc[1][1] = ffma2(s, rv3.y, acc[1][1]);

            s = fpack(pC.x, pC.x); acc[2][0] = ffma2(s, rv0.x, acc[2][0]); acc[2][1] = ffma2(s, rv0.y, acc[2][1]);
            s = fpack(pC.y, pC.y); acc[2][0] = ffma2(s, rv1.x, acc[2][0]); acc[2][1] = ffma2(s, rv1.y, acc[2][1]);
            s = fpack(pC.z, pC.z); acc[2][0] = ffma2(s, rv2.x, acc[2][0]); acc[2][1] = ffma2(s, rv2.y, acc[2][1]);
            s = fpack(pC.w, pC.w); acc[2][0] = ffma2(s, rv3.x, acc[2][0]); acc[2][1] = ffma2(s, rv3.y, acc[2][1]);
        }
    }

    __syncthreads();
    float* red = &rvs[0][0];
    #pragma unroll
    for (int j = 0; j < 3; j++) {
        float2 lo = funpack(acc[j][0]);
        float2 hi = funpack(acc[j][1]);
        red[tid * 12 + j * 4 + 0] = lo.x;
        red[tid * 12 + j * 4 + 1] = lo.y;
        red[tid * 12 + j * 4 + 2] = hi.x;
        red[tid * 12 + j * 4 + 3] = hi.y;
    }
    __syncthreads();

    if (tid < 64) {
        const int quad_ = tid & 15;
        const int hg_   = tid >> 4;
        #pragma unroll
        for (int j = 0; j < 3; j++) {
            int hh = hg_ + 4 * j;
            float4 sum = make_float4(0.f, 0.f, 0.f, 0.f);
            #pragma unroll
            for (int s4 = 0; s4 < 4; s4++) {
                const float* r = red + (size_t)(tid + 64 * s4) * 12 + j * 4;
                sum.x += r[0]; sum.y += r[1]; sum.z += r[2]; sum.w += r[3];
            }
            size_t idx = (size_t)(b * SQ + q) * DM + hh * DK + quad_ * 4;
            float4 a1 = *(const float4*)(g_attn + idx);
            float4 a2 = *(const float4*)(g_attn2 + idx);
            sum.x += a1.x + a2.x; sum.y += a1.y + a2.y;
            sum.z += a1.z + a2.z; sum.w += a1.w + a2.w;
            *(float4*)(g_attn + idx) = sum;
        }
    }
}

// =====================================================================
// K7: output projection. grid (16, 12).
// =====================================================================
__global__ __launch_bounds__(256) void k_out(
    const float* __restrict__ Wo, const float* __restrict__ bo, float* __restrict__ out)
{
    __shared__ __align__(16) float As[16][128];
    __shared__ __align__(16) float Bs[16][64];

    const int tid = threadIdx.x;
    const int tx = tid & 15, ty = tid >> 4;
    const int m0 = blockIdx.x * 128;
    const int n0 = blockIdx.y * 64;

    u64 acc[8][2];
    #pragma unroll
    for (int i = 0; i < 8; i++) { acc[i][0] = 0ull; acc[i][1] = 0ull; }

    float4 pfa[2], pfb;
    #pragma unroll
    for (int it = 0; it < 2; it++) {
        int f = tid + it * 256;
        pfa[it] = *(const float4*)(g_attn + (size_t)(m0 + (f >> 2)) * DM + (f & 3) * 4);
    }
    pfb = *(const float4*)(Wo + (size_t)(tid >> 4) * DM + n0 + (tid & 15) * 4);

    for (int k0 = 0; k0 < DM; k0 += 16) {
        __syncthreads();
        #pragma unroll
        for (int it = 0; it < 2; it++) {
            int f = tid + it * 256;
            int m = f >> 2;
            int kk = (f & 3) * 4;
            As[kk + 0][m] = pfa[it].x; As[kk + 1][m] = pfa[it].y;
            As[kk + 2][m] = pfa[it].z; As[kk + 3][m] = pfa[it].w;
        }
        *(float4*)&Bs[tid >> 4][(tid & 15) * 4] = pfb;
        __syncthreads();

        if (k0 + 16 < DM) {
            #pragma unroll
            for (int it = 0; it < 2; it++) {
                int f = tid + it * 256;
                pfa[it] = *(const float4*)(g_attn + (size_t)(m0 + (f >> 2)) * DM + k0 + 16 + (f & 3) * 4);
            }
            pfb = *(const float4*)(Wo + (size_t)(k0 + 16 + (tid >> 4)) * DM + n0 + (tid & 15) * 4);
        }

        #pragma unroll
        for (int k = 0; k < 16; k++) {
            float4 a0 = *(const float4*)&As[k][ty * 8];
            float4 a1 = *(const float4*)&As[k][ty * 8 + 4];
            ulonglong2 bu = *(const ulonglong2*)&Bs[k][tx * 4];
            float a[8] = {a0.x, a0.y, a0.z, a0.w, a1.x, a1.y, a1.z, a1.w};
            #pragma unroll
            for (int i = 0; i < 8; i++) {
                u64 ad = fpack(a[i], a[i]);
                acc[i][0] = ffma2(ad, bu.x, acc[i][0]);
                acc[i][1] = ffma2(ad, bu.y, acc[i][1]);
            }
        }
    }

    float4 bb = *(const float4*)(bo + n0 + tx * 4);
    #pragma unroll
    for (int i = 0; i < 8; i++) {
        int m = m0 + ty * 8 + i;
        float2 p0 = funpack(acc[i][0]);
        float2 p1 = funpack(acc[i][1]);
        float4 o = make_float4(p0.x + bb.x, p0.y + bb.y, p1.x + bb.z, p1.y + bb.w);
        *(float4*)(out + (size_t)m * DM + n0 + tx * 4) = o;
    }
}

// =====================================================================
extern "C" void kernel_launch(void* const* d_in, const int* in_sizes, int n_in,
                              void* d_out, int out_size)
{
    const float* queries = (const float*)d_in[0];
    const float* keys    = (const float*)d_in[1];
    const float* values  = (const float*)d_in[2];
    const float* relk    = (const float*)d_in[3];
    const float* relv    = (const float*)d_in[4];
    const float* Wq = (const float*)d_in[5];
    const float* bq = (const float*)d_in[6];
    const float* Wk = (const float*)d_in[7];
    const float* bk = (const float*)d_in[8];
    const float* Wv = (const float*)d_in[9];
    const float* bv = (const float*)d_in[10];
    const float* Wo = (const float*)d_in[11];
    const float* bo = (const float*)d_in[12];
    float* out = (float*)d_out;

    static bool attr_set = false;
    if (!attr_set) {
        cudaFuncSetAttribute(k_qk, cudaFuncAttributeMaxDynamicSharedMemorySize,
                             2 * 128 * 68 * (int)sizeof(u32));
        cudaFuncSetAttribute(k_qrel_sm, cudaFuncAttributeMaxDynamicSharedMemorySize,
                             (NH * SQ + 128 * 68 + NH * DK) * (int)sizeof(float));
        attr_set = true;
    }

    k_proj<<<dim3(16, 12, 3), 256>>>(queries, keys, values, Wq, Wk, Wv, bq, bk, bv);
    k_qk<<<dim3(8, 8, NB * NH), 256, 2 * 128 * 68 * sizeof(u32)>>>();
    k_qrel_sm<<<dim3(SQ, NB), 512,
                (NH * SQ + 128 * 68 + NH * DK) * sizeof(float)>>>(relk);
    k_wv<<<dim3(8, NB * NH, 2), 256>>>();
    k_wrel<<<dim3(SQ, NB), 256>>>(relv);
    k_out<<<dim3(16, 12), 256>>>(Wo, bo, out);
}

// round 8
// speedup vs baseline: 1.7416x; 1.1685x over previous
#include <cuda_runtime.h>

typedef unsigned long long u64;
typedef unsigned int u32;

#define NB 2
#define NH 12
#define SQ 1024
#define DK 64
#define DM 768

// ---------------- scratch ----------------
__device__ float g_q[NB*NH*SQ*DK];                 // pre-scaled by 1/64
__device__ float g_k[NB*NH*SQ*DK];
__device__ float g_v[NB*NH*SQ*DK];
__device__ float g_scores[(size_t)NB*NH*SQ*SQ];    // scores, then probs (in place)
__device__ float g_attn[NB*SQ*DM];                 // wv partial (k 0..511)
__device__ float g_attn2[NB*SQ*DM];                // wv partial (k 512..1023)

// ---------------- packed f32x2 helpers ----------------
__device__ __forceinline__ u64 fpack(float x, float y){
    u64 r; asm("mov.b64 %0,{%1,%2};" : "=l"(r) : "f"(x), "f"(y)); return r;
}
__device__ __forceinline__ u64 ffma2(u64 a, u64 b, u64 c){
    u64 d; asm("fma.rn.f32x2 %0,%1,%2,%3;" : "=l"(d) : "l"(a), "l"(b), "l"(c)); return d;
}
__device__ __forceinline__ float2 funpack(u64 v){
    float x, y; asm("mov.b64 {%0,%1},%2;" : "=f"(x), "=f"(y) : "l"(v)); return make_float2(x, y);
}

// ---------------- tf32 mma helpers ----------------
__device__ __forceinline__ u32 to_tf32(float f){
    u32 u; asm("cvt.rna.tf32.f32 %0, %1;" : "=r"(u) : "f"(f)); return u;
}
__device__ __forceinline__ uint4 cvt4(float4 v){
    uint4 u; u.x = to_tf32(v.x); u.y = to_tf32(v.y); u.z = to_tf32(v.z); u.w = to_tf32(v.w);
    return u;
}
__device__ __forceinline__ void mma_tf32(float* c, const u32* a, const u32* b){
    asm volatile(
        "mma.sync.aligned.m16n8k8.row.col.f32.tf32.tf32.f32 "
        "{%0,%1,%2,%3}, {%4,%5,%6,%7}, {%8,%9}, {%0,%1,%2,%3};"
        : "+f"(c[0]), "+f"(c[1]), "+f"(c[2]), "+f"(c[3])
        : "r"(a[0]), "r"(a[1]), "r"(a[2]), "r"(a[3]), "r"(b[0]), "r"(b[1]));
}

// =====================================================================
// K1: QKV projections. grid (16, 12, 3)
// =====================================================================
__global__ __launch_bounds__(256) void k_proj(
    const float* __restrict__ Xq, const float* __restrict__ Xk, const float* __restrict__ Xv,
    const float* __restrict__ Wq, const float* __restrict__ Wk, const float* __restrict__ Wv,
    const float* __restrict__ bq, const float* __restrict__ bk, const float* __restrict__ bv)
{
    const int z = blockIdx.z;
    const float* X    = (z == 0) ? Xq : (z == 1) ? Xk : Xv;
    const float* W    = (z == 0) ? Wq : (z == 1) ? Wk : Wv;
    const float* bias = (z == 0) ? bq : (z == 1) ? bk : bv;
    float* out        = (z == 0) ? g_q : (z == 1) ? g_k : g_v;
    const float scale = (z == 0) ? (1.0f / 64.0f) : 1.0f;

    __shared__ __align__(16) float As[16][128];
    __shared__ __align__(16) float Bs[16][64];

    const int tid = threadIdx.x;
    const int tx = tid & 15, ty = tid >> 4;
    const int m0 = blockIdx.x * 128;
    const int h  = blockIdx.y;
    const int n0 = h * 64;

    u64 acc[8][2];
    #pragma unroll
    for (int i = 0; i < 8; i++) { acc[i][0] = 0ull; acc[i][1] = 0ull; }

    float4 pfa[2], pfb;
    {
        #pragma unroll
        for (int it = 0; it < 2; it++) {
            int f = tid + it * 256;
            pfa[it] = *(const float4*)(X + (size_t)(m0 + (f >> 2)) * DM + (f & 3) * 4);
        }
        pfb = *(const float4*)(W + (size_t)(tid >> 4) * DM + n0 + (tid & 15) * 4);
    }

    for (int k0 = 0; k0 < DM; k0 += 16) {
        __syncthreads();
        #pragma unroll
        for (int it = 0; it < 2; it++) {
            int f = tid + it * 256;
            int m = f >> 2;
            int kk = (f & 3) * 4;
            As[kk + 0][m] = pfa[it].x; As[kk + 1][m] = pfa[it].y;
            As[kk + 2][m] = pfa[it].z; As[kk + 3][m] = pfa[it].w;
        }
        *(float4*)&Bs[tid >> 4][(tid & 15) * 4] = pfb;
        __syncthreads();

        if (k0 + 16 < DM) {
            #pragma unroll
            for (int it = 0; it < 2; it++) {
                int f = tid + it * 256;
                pfa[it] = *(const float4*)(X + (size_t)(m0 + (f >> 2)) * DM + k0 + 16 + (f & 3) * 4);
            }
            pfb = *(const float4*)(W + (size_t)(k0 + 16 + (tid >> 4)) * DM + n0 + (tid & 15) * 4);
        }

        #pragma unroll
        for (int k = 0; k < 16; k++) {
            float4 a0 = *(const float4*)&As[k][ty * 8];
            float4 a1 = *(const float4*)&As[k][ty * 8 + 4];
            ulonglong2 bu = *(const ulonglong2*)&Bs[k][tx * 4];
            float a[8] = {a0.x, a0.y, a0.z, a0.w, a1.x, a1.y, a1.z, a1.w};
            #pragma unroll
            for (int i = 0; i < 8; i++) {
                u64 ad = fpack(a[i], a[i]);
                acc[i][0] = ffma2(ad, bu.x, acc[i][0]);
                acc[i][1] = ffma2(ad, bu.y, acc[i][1]);
            }
        }
    }

    float4 bb = *(const float4*)(bias + n0 + tx * 4);
    #pragma unroll
    for (int i = 0; i < 8; i++) {
        int m = m0 + ty * 8 + i;
        int b = m >> 10;
        int s = m & (SQ - 1);
        float2 p0 = funpack(acc[i][0]);
        float2 p1 = funpack(acc[i][1]);
        float4 o;
        o.x = (p0.x + bb.x) * scale;
        o.y = (p0.y + bb.y) * scale;
        o.z = (p1.x + bb.z) * scale;
        o.w = (p1.y + bb.w) * scale;
        *(float4*)(out + ((size_t)((b * NH + h) * SQ + s)) * DK + tx * 4) = o;
    }
}

// =====================================================================
// K2: scores = q @ k^T per (b,h) via tf32 mma. CTA tile 128x128.
// grid (8, 8, 24), dyn smem 69632 B.
// =====================================================================
__global__ __launch_bounds__(256) void k_qk()
{
    extern __shared__ __align__(16) u32 smu[];
    u32 (*Qs)[68] = (u32(*)[68])smu;
    u32 (*Ks)[68] = (u32(*)[68])(smu + 128 * 68);

    const int bh = blockIdx.z;
    const float* Aq = g_q + (size_t)bh * SQ * DK;
    const float* Bk = g_k + (size_t)bh * SQ * DK;
    float* C = g_scores + (size_t)bh * SQ * SQ;

    const int m0 = blockIdx.x * 128;
    const int n0 = blockIdx.y * 128;
    const int tid = threadIdx.x;
    const int lane = tid & 31;
    const int warp = tid >> 5;
    const int wm = warp >> 2;
    const int wn = warp & 3;
    const int rq = lane >> 2;
    const int cq = lane & 3;

    #pragma unroll
    for (int it = 0; it < 8; it++) {
        int f = tid + it * 256;
        int r  = f >> 4;
        int d4 = (f & 15) * 4;
        float4 va = *(const float4*)(Aq + (size_t)(m0 + r) * DK + d4);
        float4 vb = *(const float4*)(Bk + (size_t)(n0 + r) * DK + d4);
        *(uint4*)&Qs[r][d4] = cvt4(va);
        *(uint4*)&Ks[r][d4] = cvt4(vb);
    }
    __syncthreads();

    float acc[4][4][4];
    #pragma unroll
    for (int i = 0; i < 4; i++)
        #pragma unroll
        for (int j = 0; j < 4; j++)
            #pragma unroll
            for (int t = 0; t < 4; t++) acc[i][j][t] = 0.f;

    #pragma unroll
    for (int ks = 0; ks < 8; ks++) {
        int d0 = ks * 8;
        u32 a[4][4], bf[4][2];
        #pragma unroll
        for (int mi = 0; mi < 4; mi++) {
            int r = wm * 64 + mi * 16 + rq;
            a[mi][0] = Qs[r][d0 + cq];
            a[mi][1] = Qs[r + 8][d0 + cq];
            a[mi][2] = Qs[r][d0 + cq + 4];
            a[mi][3] = Qs[r + 8][d0 + cq + 4];
        }
        #pragma unroll
        for (int ni = 0; ni < 4; ni++) {
            int n = wn * 32 + ni * 8 + rq;
            bf[ni][0] = Ks[n][d0 + cq];
            bf[ni][1] = Ks[n][d0 + cq + 4];
        }
        #pragma unroll
        for (int mi = 0; mi < 4; mi++)
            #pragma unroll
            for (int ni = 0; ni < 4; ni++)
                mma_tf32(acc[mi][ni], a[mi], bf[ni]);
    }

    #pragma unroll
    for (int mi = 0; mi < 4; mi++) {
        #pragma unroll
        for (int ni = 0; ni < 4; ni++) {
            int r0 = m0 + wm * 64 + mi * 16 + rq;
            int c0 = n0 + wn * 32 + ni * 8 + cq * 2;
            *(float2*)(C + (size_t)r0 * SQ + c0)       = make_float2(acc[mi][ni][0], acc[mi][ni][1]);
            *(float2*)(C + (size_t)(r0 + 8) * SQ + c0) = make_float2(acc[mi][ni][2], acc[mi][ni][3]);
        }
    }
}

// =====================================================================
// K3 (fused): per (b,q): scores += q . relation_k (tf32 mma), softmax.
// 512 threads = 16 warps; warp w handles chunk cols [w*8, w*8+8).
// A-fragments (q) hoisted out of the chunk loop.
// grid (1024, 2), dyn smem 88064 B.
// =====================================================================
__global__ __launch_bounds__(512) void k_qrel_sm(const float* __restrict__ relk)
{
    extern __shared__ __align__(16) float sm[];
    float* ss = sm;                                        // 12*1024 floats
    u32 (*rks)[68] = (u32(*)[68])(sm + NH * SQ);           // 128*68 tf32
    u32 (*qs)[64] = (u32(*)[64])(sm + NH * SQ + 128 * 68); // 16*64 tf32 (rows 12-15 zero)

    const int b = blockIdx.y, q = blockIdx.x;
    const int tid = threadIdx.x;
    const int lane = tid & 31;
    const int warp = tid >> 5;       // 0..15
    const int rq = lane >> 2;        // 0..7
    const int cq = lane & 3;         // 0..3
    const int n0c = warp * 8;

    // load q rows (12 heads x 64) as tf32; zero pad rows 12..15
    if (tid < 192) {
        int hh = tid >> 4;
        int d4 = (tid & 15) * 4;
        float4 v = *(const float4*)(g_q + ((size_t)((b * NH + hh) * SQ + q)) * DK + d4);
        *(uint4*)&qs[hh][d4] = cvt4(v);
    } else if (tid < 256) {
        int r = 12 + ((tid - 192) >> 4);
        int d4 = ((tid - 192) & 15) * 4;
        *(uint4*)&qs[r][d4] = make_uint4(0u, 0u, 0u, 0u);
    }
    // load raw qk scores for all 12 heads
    #pragma unroll
    for (int it = 0; it < 6; it++) {
        int f = tid + it * 512;
        int hh = f >> 8;
        int k4 = (f & 255) * 4;
        *(float4*)&ss[hh * SQ + k4] =
            *(const float4*)(g_scores + ((size_t)((b * NH + hh) * SQ + q)) * SQ + k4);
    }

    const float* relbase = relk + ((size_t)(b * SQ + q)) * SQ * DK;

    float4 pf[4];
    #pragma unroll
    for (int it = 0; it < 4; it++) {
        int f = tid + it * 512;
        pf[it] = *(const float4*)(relbase + (size_t)(f >> 4) * DK + (f & 15) * 4);
    }
    __syncthreads();   // qs ready

    // hoist A fragments (q is constant across chunks)
    u32 afrag[8][4];
    #pragma unroll
    for (int ks = 0; ks < 8; ks++) {
        int d0 = ks * 8;
        afrag[ks][0] = qs[rq][d0 + cq];
        afrag[ks][1] = qs[rq + 8][d0 + cq];
        afrag[ks][2] = qs[rq][d0 + cq + 4];
        afrag[ks][3] = qs[rq + 8][d0 + cq + 4];
    }

    for (int kt = 0; kt < SQ; kt += 128) {
        __syncthreads();
        #pragma unroll
        for (int it = 0; it < 4; it++) {
            int f = tid + it * 512;
            *(uint4*)&rks[f >> 4][(f & 15) * 4] = cvt4(pf[it]);
        }
        __syncthreads();

        if (kt + 128 < SQ) {
            #pragma unroll
            for (int it = 0; it < 4; it++) {
                int f = tid + it * 512;
                pf[it] = *(const float4*)(relbase + (size_t)(kt + 128 + (f >> 4)) * DK + (f & 15) * 4);
            }
        }

        float acc[4] = {0.f, 0.f, 0.f, 0.f};
        #pragma unroll
        for (int ks = 0; ks < 8; ks++) {
            int d0 = ks * 8;
            u32 bf[2];
            bf[0] = rks[n0c + rq][d0 + cq];
            bf[1] = rks[n0c + rq][d0 + cq + 4];
            mma_tf32(acc, afrag[ks], bf);
        }

        int col = kt + n0c + cq * 2;
        ss[rq * SQ + col]     += acc[0];
        ss[rq * SQ + col + 1] += acc[1];
        if (rq < 4) {
            ss[(rq + 8) * SQ + col]     += acc[2];
            ss[(rq + 8) * SQ + col + 1] += acc[3];
        }
    }
    __syncthreads();

    // softmax per head-row, write probs
    const int swarp = tid >> 5;
    const int slane = tid & 31;
    if (swarp < NH) {
        float* p = ss + swarp * SQ;
        float4 v[8];
        float mx = -3.4e38f;
        #pragma unroll
        for (int j = 0; j < 8; j++) {
            v[j] = *(float4*)(p + slane * 4 + j * 128);
            mx = fmaxf(mx, fmaxf(fmaxf(v[j].x, v[j].y), fmaxf(v[j].z, v[j].w)));
        }
        #pragma unroll
        for (int o = 16; o > 0; o >>= 1) mx = fmaxf(mx, __shfl_xor_sync(0xffffffffu, mx, o));

        float s = 0.f;
        #pragma unroll
        for (int j = 0; j < 8; j++) {
            v[j].x = __expf(v[j].x - mx);
            v[j].y = __expf(v[j].y - mx);
            v[j].z = __expf(v[j].z - mx);
            v[j].w = __expf(v[j].w - mx);
            s += v[j].x + v[j].y + v[j].z + v[j].w;
        }
        #pragma unroll
        for (int o = 16; o > 0; o >>= 1) s += __shfl_xor_sync(0xffffffffu, s, o);
        const float inv = 1.0f / s;

        float* dst = g_scores + ((size_t)((b * NH + swarp) * SQ + q)) * SQ;
        #pragma unroll
        for (int j = 0; j < 8; j++) {
            v[j].x *= inv; v[j].y *= inv; v[j].z *= inv; v[j].w *= inv;
            *(float4*)(dst + slane * 4 + j * 128) = v[j];
        }
    }
}

// =====================================================================
// K5: wv = probs @ v per (b,h) via tf32 mma. split-K=2. grid (8,24,2).
// =====================================================================
__global__ __launch_bounds__(256) void k_wv()
{
    __shared__ __align__(16) u32 As[128][36];
    __shared__ __align__(16) u32 Bs[32][72];

    const int bh = blockIdx.y;
    const int b = bh / NH, h = bh % NH;
    const int koff = blockIdx.z * 512;
    const float* A  = g_scores + (size_t)bh * SQ * SQ + koff;
    const float* Bv = g_v + ((size_t)bh * SQ + koff) * DK;
    float* outp = blockIdx.z ? g_attn2 : g_attn;

    const int m0 = blockIdx.x * 128;
    const int tid = threadIdx.x;
    const int lane = tid & 31;
    const int warp = tid >> 5;
    const int wm = warp >> 1;
    const int wn = warp & 1;
    const int rq = lane >> 2;
    const int cq = lane & 3;

    float acc[2][4][4];
    #pragma unroll
    for (int i = 0; i < 2; i++)
        #pragma unroll
        for (int j = 0; j < 4; j++)
            #pragma unroll
            for (int t = 0; t < 4; t++) acc[i][j][t] = 0.f;

    float4 pfa[4], pfb[2];
    #pragma unroll
    for (int it = 0; it < 4; it++) {
        int f = tid + it * 256;
        pfa[it] = *(const float4*)(A + (size_t)(m0 + (f >> 3)) * SQ + (f & 7) * 4);
    }
    #pragma unroll
    for (int it = 0; it < 2; it++) {
        int f = tid + it * 256;
        pfb[it] = *(const float4*)(Bv + (size_t)(f >> 4) * DK + (f & 15) * 4);
    }

    for (int k0 = 0; k0 < 512; k0 += 32) {
        __syncthreads();
        #pragma unroll
        for (int it = 0; it < 4; it++) {
            int f = tid + it * 256;
            *(uint4*)&As[f >> 3][(f & 7) * 4] = cvt4(pfa[it]);
        }
        #pragma unroll
        for (int it = 0; it < 2; it++) {
            int f = tid + it * 256;
            *(uint4*)&Bs[f >> 4][(f & 15) * 4] = cvt4(pfb[it]);
        }
        __syncthreads();

        if (k0 + 32 < 512) {
            #pragma unroll
            for (int it = 0; it < 4; it++) {
                int f = tid + it * 256;
                pfa[it] = *(const float4*)(A + (size_t)(m0 + (f >> 3)) * SQ + k0 + 32 + (f & 7) * 4);
            }
            #pragma unroll
            for (int it = 0; it < 2; it++) {
                int f = tid + it * 256;
                pfb[it] = *(const float4*)(Bv + (size_t)(k0 + 32 + (f >> 4)) * DK + (f & 15) * 4);
            }
        }

        #pragma unroll
        for (int ks = 0; ks < 4; ks++) {
            int kk = ks * 8;
            u32 a[2][4], bf[4][2];
            #pragma unroll
            for (int mi = 0; mi < 2; mi++) {
                int r = wm * 32 + mi * 16 + rq;
                a[mi][0] = As[r][kk + cq];
                a[mi][1] = As[r + 8][kk + cq];
                a[mi][2] = As[r][kk + cq + 4];
                a[mi][3] = As[r + 8][kk + cq + 4];
            }
            #pragma unroll
            for (int ni = 0; ni < 4; ni++) {
                int n = wn * 32 + ni * 8 + rq;
                bf[ni][0] = Bs[kk + cq][n];
                bf[ni][1] = Bs[kk + cq + 4][n];
            }
            #pragma unroll
            for (int mi = 0; mi < 2; mi++)
                #pragma unroll
                for (int ni = 0; ni < 4; ni++)
                    mma_tf32(acc[mi][ni], a[mi], bf[ni]);
        }
    }

    #pragma unroll
    for (int mi = 0; mi < 2; mi++) {
        #pragma unroll
        for (int ni = 0; ni < 4; ni++) {
            int r0 = m0 + wm * 32 + mi * 16 + rq;
            int c0 = wn * 32 + ni * 8 + cq * 2;
            float* dst0 = outp + (size_t)(b * SQ + r0) * DM + h * DK + c0;
            float* dst1 = outp + (size_t)(b * SQ + r0 + 8) * DM + h * DK + c0;
            *(float2*)dst0 = make_float2(acc[mi][ni][0], acc[mi][ni][1]);
            *(float2*)dst1 = make_float2(acc[mi][ni][2], acc[mi][ni][3]);
        }
    }
}

// =====================================================================
// K6: g_attn = g_attn + g_attn2 + probs @ relation_v via tf32 mma.
// 256 threads = 8 warps; warp w owns d-cols [w*8, w*8+8), acc chained
// across all k. grid (1024, 2).
// =====================================================================
__global__ __launch_bounds__(256) void k_wrel(const float* __restrict__ relv)
{
    __shared__ __align__(16) u32 rvs[128][72];   // relV chunk tf32 [k][d]
    __shared__ __align__(16) u32 ps[16][132];    // probs chunk tf32 [h][k], rows 12-15 zero

    const int b = blockIdx.y, q = blockIdx.x;
    const int tid = threadIdx.x;
    const int lane = tid & 31;
    const int warp = tid >> 5;       // 0..7
    const int rq = lane >> 2;
    const int cq = lane & 3;
    const int n0c = warp * 8;

    // zero pad rows 12..15 of ps (cols 0..127)
    {
        int r = 12 + (tid >> 6);
        int c = (tid & 63) * 2;
        ps[r][c] = 0u; ps[r][c + 1] = 0u;
    }

    const float* relbase = relv + ((size_t)(b * SQ + q)) * SQ * DK;
    const float* psrc = g_scores + ((size_t)(b * NH) * SQ + q) * SQ;

    float acc[4] = {0.f, 0.f, 0.f, 0.f};

    float4 pfr[8], pfp[2];
    #pragma unroll
    for (int it = 0; it < 8; it++) {
        int f = tid + it * 256;
        pfr[it] = *(const float4*)(relbase + (size_t)(f >> 4) * DK + (f & 15) * 4);
    }
    #pragma unroll
    for (int it = 0; it < 2; it++) {
        int f = tid + it * 256;
        if (f < 384)
            pfp[it] = *(const float4*)(psrc + (size_t)(f >> 5) * SQ * SQ + (f & 31) * 4);
    }

    for (int kt = 0; kt < SQ; kt += 128) {
        __syncthreads();
        #pragma unroll
        for (int it = 0; it < 8; it++) {
            int f = tid + it * 256;
            *(uint4*)&rvs[f >> 4][(f & 15) * 4] = cvt4(pfr[it]);
        }
        #pragma unroll
        for (int it = 0; it < 2; it++) {
            int f = tid + it * 256;
            if (f < 384)
                *(uint4*)&ps[f >> 5][(f & 31) * 4] = cvt4(pfp[it]);
        }
        __syncthreads();

        if (kt + 128 < SQ) {
            #pragma unroll
            for (int it = 0; it < 8; it++) {
                int f = tid + it * 256;
                pfr[it] = *(const float4*)(relbase + (size_t)(kt + 128 + (f >> 4)) * DK + (f & 15) * 4);
            }
            #pragma unroll
            for (int it = 0; it < 2; it++) {
                int f = tid + it * 256;
                if (f < 384)
                    pfp[it] = *(const float4*)(psrc + (size_t)(f >> 5) * SQ * SQ + kt + 128 + (f & 31) * 4);
            }
        }

        #pragma unroll
        for (int ks = 0; ks < 16; ks++) {
            int kk = ks * 8;
            u32 a[4], bf[2];
            a[0] = ps[rq][kk + cq];
            a[1] = ps[rq + 8][kk + cq];
            a[2] = ps[rq][kk + cq + 4];
            a[3] = ps[rq + 8][kk + cq + 4];
            bf[0] = rvs[kk + cq][n0c + rq];
            bf[1] = rvs[kk + cq + 4][n0c + rq];
            mma_tf32(acc, a, bf);
        }
    }

    // write out: rows = heads, cols = d. add the two wv partials.
    const size_t base = (size_t)(b * SQ + q) * DM;
    const int col = n0c + cq * 2;
    {
        size_t idx = base + rq * DK + col;
        float2 a1 = *(const float2*)(g_attn + idx);
        float2 a2 = *(const float2*)(g_attn2 + idx);
        *(float2*)(g_attn + idx) = make_float2(acc[0] + a1.x + a2.x, acc[1] + a1.y + a2.y);
    }
    if (rq < 4) {
        size_t idx = base + (rq + 8) * DK + col;
        float2 a1 = *(const float2*)(g_attn + idx);
        float2 a2 = *(const float2*)(g_attn2 + idx);
        *(float2*)(g_attn + idx) = make_float2(acc[2] + a1.x + a2.x, acc[3] + a1.y + a2.y);
    }
}

// =====================================================================
// K7: output projection. grid (16, 12).
// =====================================================================
__global__ __launch_bounds__(256) void k_out(
    const float* __restrict__ Wo, const float* __restrict__ bo, float* __restrict__ out)
{
    __shared__ __align__(16) float As[16][128];
    __shared__ __align__(16) float Bs[16][64];

    const int tid = threadIdx.x;
    const int tx = tid & 15, ty = tid >> 4;
    const int m0 = blockIdx.x * 128;
    const int n0 = blockIdx.y * 64;

    u64 acc[8][2];
    #pragma unroll
    for (int i = 0; i < 8; i++) { acc[i][0] = 0ull; acc[i][1] = 0ull; }

    float4 pfa[2], pfb;
    #pragma unroll
    for (int it = 0; it < 2; it++) {
        int f = tid + it * 256;
        pfa[it] = *(const float4*)(g_attn + (size_t)(m0 + (f >> 2)) * DM + (f & 3) * 4);
    }
    pfb = *(const float4*)(Wo + (size_t)(tid >> 4) * DM + n0 + (tid & 15) * 4);

    for (int k0 = 0; k0 < DM; k0 += 16) {
        __syncthreads();
        #pragma unroll
        for (int it = 0; it < 2; it++) {
            int f = tid + it * 256;
            int m = f >> 2;
            int kk = (f & 3) * 4;
            As[kk + 0][m] = pfa[it].x; As[kk + 1][m] = pfa[it].y;
            As[kk + 2][m] = pfa[it].z; As[kk + 3][m] = pfa[it].w;
        }
        *(float4*)&Bs[tid >> 4][(tid & 15) * 4] = pfb;
        __syncthreads();

        if (k0 + 16 < DM) {
            #pragma unroll
            for (int it = 0; it < 2; it++) {
                int f = tid + it * 256;
                pfa[it] = *(const float4*)(g_attn + (size_t)(m0 + (f >> 2)) * DM + k0 + 16 + (f & 3) * 4);
            }
            pfb = *(const float4*)(Wo + (size_t)(k0 + 16 + (tid >> 4)) * DM + n0 + (tid & 15) * 4);
        }

        #pragma unroll
        for (int k = 0; k < 16; k++) {
            float4 a0 = *(const float4*)&As[k][ty * 8];
            float4 a1 = *(const float4*)&As[k][ty * 8 + 4];
            ulonglong2 bu = *(const ulonglong2*)&Bs[k][tx * 4];
            float a[8] = {a0.x, a0.y, a0.z, a0.w, a1.x, a1.y, a1.z, a1.w};
            #pragma unroll
            for (int i = 0; i < 8; i++) {
                u64 ad = fpack(a[i], a[i]);
                acc[i][0] = ffma2(ad, bu.x, acc[i][0]);
                acc[i][1] = ffma2(ad, bu.y, acc[i][1]);
            }
        }
    }

    float4 bb = *(const float4*)(bo + n0 + tx * 4);
    #pragma unroll
    for (int i = 0; i < 8; i++) {
        int m = m0 + ty * 8 + i;
        float2 p0 = funpack(acc[i][0]);
        float2 p1 = funpack(acc[i][1]);
        float4 o = make_float4(p0.x + bb.x, p0.y + bb.y, p1.x + bb.z, p1.y + bb.w);
        *(float4*)(out + (size_t)m * DM + n0 + tx * 4) = o;
    }
}

// =====================================================================
extern "C" void kernel_launch(void* const* d_in, const int* in_sizes, int n_in,
                              void* d_out, int out_size)
{
    const float* queries = (const float*)d_in[0];
    const float* keys    = (const float*)d_in[1];
    const float* values  = (const float*)d_in[2];
    const float* relk    = (const float*)d_in[3];
    const float* relv    = (const float*)d_in[4];
    const float* Wq = (const float*)d_in[5];
    const float* bq = (const float*)d_in[6];
    const float* Wk = (const float*)d_in[7];
    const float* bk = (const float*)d_in[8];
    const float* Wv = (const float*)d_in[9];
    const float* bv = (const float*)d_in[10];
    const float* Wo = (const float*)d_in[11];
    const float* bo = (const float*)d_in[12];
    float* out = (float*)d_out;

    const int qrel_smem = NH * SQ * (int)sizeof(float)
                        + 128 * 68 * (int)sizeof(u32)
                        + 16 * 64 * (int)sizeof(u32);

    static bool attr_set = false;
    if (!attr_set) {
        cudaFuncSetAttribute(k_qk, cudaFuncAttributeMaxDynamicSharedMemorySize,
                             2 * 128 * 68 * (int)sizeof(u32));
        cudaFuncSetAttribute(k_qrel_sm, cudaFuncAttributeMaxDynamicSharedMemorySize,
                             qrel_smem);
        attr_set = true;
    }

    k_proj<<<dim3(16, 12, 3), 256>>>(queries, keys, values, Wq, Wk, Wv, bq, bk, bv);
    k_qk<<<dim3(8, 8, NB * NH), 256, 2 * 128 * 68 * sizeof(u32)>>>();
    k_qrel_sm<<<dim3(SQ, NB), 512, qrel_smem>>>(relk);
    k_wv<<<dim3(8, NB * NH, 2), 256>>>();
    k_wrel<<<dim3(SQ, NB), 256>>>(relv);
    k_out<<<dim3(16, 12), 256>>>(Wo, bo, out);
}

// round 9
// speedup vs baseline: 2.1802x; 1.2518x over previous
#include <cuda_runtime.h>

typedef unsigned long long u64;
typedef unsigned int u32;

#define NB 2
#define NH 12
#define SQ 1024
#define DK 64
#define DM 768

// ---------------- scratch ----------------
__device__ float g_q[NB*NH*SQ*DK];                 // pre-scaled by 1/64
__device__ float g_k[NB*NH*SQ*DK];
__device__ float g_v[NB*NH*SQ*DK];
__device__ float g_scores[(size_t)NB*NH*SQ*SQ];    // scores, then probs (in place)
__device__ float g_attn[NB*SQ*DM];                 // wv partial (k 0..511)
__device__ float g_attn2[NB*SQ*DM];                // wv partial (k 512..1023)

// ---------------- tf32 mma helpers ----------------
__device__ __forceinline__ u32 to_tf32(float f){
    u32 u; asm("cvt.rna.tf32.f32 %0, %1;" : "=r"(u) : "f"(f)); return u;
}
__device__ __forceinline__ uint4 cvt4(float4 v){
    uint4 u; u.x = to_tf32(v.x); u.y = to_tf32(v.y); u.z = to_tf32(v.z); u.w = to_tf32(v.w);
    return u;
}
__device__ __forceinline__ void mma_tf32(float* c, const u32* a, const u32* b){
    asm volatile(
        "mma.sync.aligned.m16n8k8.row.col.f32.tf32.tf32.f32 "
        "{%0,%1,%2,%3}, {%4,%5,%6,%7}, {%8,%9}, {%0,%1,%2,%3};"
        : "+f"(c[0]), "+f"(c[1]), "+f"(c[2]), "+f"(c[3])
        : "r"(a[0]), "r"(a[1]), "r"(a[2]), "r"(a[3]), "r"(b[0]), "r"(b[1]));
}

// =====================================================================
// K1: QKV projections via tf32 mma with split-A (2 mma) for accuracy.
// BM=128, BN=64 (one head), BK=32. 256 threads, warp grid 4(m)x2(n).
// grid (16, 12, 3).
// =====================================================================
__global__ __launch_bounds__(256) void k_proj(
    const float* __restrict__ Xq, const float* __restrict__ Xk, const float* __restrict__ Xv,
    const float* __restrict__ Wq, const float* __restrict__ Wk, const float* __restrict__ Wv,
    const float* __restrict__ bq, const float* __restrict__ bk, const float* __restrict__ bv)
{
    const int z = blockIdx.z;
    const float* X    = (z == 0) ? Xq : (z == 1) ? Xk : Xv;
    const float* W    = (z == 0) ? Wq : (z == 1) ? Wk : Wv;
    const float* bias = (z == 0) ? bq : (z == 1) ? bk : bv;
    float* out        = (z == 0) ? g_q : (z == 1) ? g_k : g_v;
    const float scale = (z == 0) ? (1.0f / 64.0f) : 1.0f;

    __shared__ __align__(16) u32 Ah[128][36];
    __shared__ __align__(16) u32 Al[128][36];
    __shared__ __align__(16) u32 Bs[32][72];

    const int tid = threadIdx.x;
    const int lane = tid & 31;
    const int warp = tid >> 5;
    const int wm = warp >> 1;    // 0..3 -> m offset *32
    const int wn = warp & 1;     // 0..1 -> n offset *32
    const int rq = lane >> 2;
    const int cq = lane & 3;
    const int m0 = blockIdx.x * 128;
    const int h  = blockIdx.y;
    const int n0 = h * 64;

    float acc[2][4][4];
    #pragma unroll
    for (int i = 0; i < 2; i++)
        #pragma unroll
        for (int j = 0; j < 4; j++)
            #pragma unroll
            for (int t = 0; t < 4; t++) acc[i][j][t] = 0.f;

    float4 pfa[4], pfb[2];
    #pragma unroll
    for (int it = 0; it < 4; it++) {
        int f = tid + it * 256;
        pfa[it] = *(const float4*)(X + (size_t)(m0 + (f >> 3)) * DM + (f & 7) * 4);
    }
    #pragma unroll
    for (int it = 0; it < 2; it++) {
        int f = tid + it * 256;
        pfb[it] = *(const float4*)(W + (size_t)(f >> 4) * DM + n0 + (f & 15) * 4);
    }

    for (int k0 = 0; k0 < DM; k0 += 32) {
        __syncthreads();
        #pragma unroll
        for (int it = 0; it < 4; it++) {
            int f = tid + it * 256;
            int m = f >> 3;
            int k4 = (f & 7) * 4;
            float4 v = pfa[it];
            uint4 hi = cvt4(v);
            float4 r;
            r.x = v.x - __uint_as_float(hi.x);
            r.y = v.y - __uint_as_float(hi.y);
            r.z = v.z - __uint_as_float(hi.z);
            r.w = v.w - __uint_as_float(hi.w);
            *(uint4*)&Ah[m][k4] = hi;
            *(uint4*)&Al[m][k4] = cvt4(r);
        }
        #pragma unroll
        for (int it = 0; it < 2; it++) {
            int f = tid + it * 256;
            *(uint4*)&Bs[f >> 4][(f & 15) * 4] = cvt4(pfb[it]);
        }
        __syncthreads();

        if (k0 + 32 < DM) {
            #pragma unroll
            for (int it = 0; it < 4; it++) {
                int f = tid + it * 256;
                pfa[it] = *(const float4*)(X + (size_t)(m0 + (f >> 3)) * DM + k0 + 32 + (f & 7) * 4);
            }
            #pragma unroll
            for (int it = 0; it < 2; it++) {
                int f = tid + it * 256;
                pfb[it] = *(const float4*)(W + (size_t)(k0 + 32 + (f >> 4)) * DM + n0 + (f & 15) * 4);
            }
        }

        #pragma unroll
        for (int ks = 0; ks < 4; ks++) {
            int kk = ks * 8;
            u32 ah[2][4], al[2][4], bf[4][2];
            #pragma unroll
            for (int mi = 0; mi < 2; mi++) {
                int r = wm * 32 + mi * 16 + rq;
                ah[mi][0] = Ah[r][kk + cq];
                ah[mi][1] = Ah[r + 8][kk + cq];
                ah[mi][2] = Ah[r][kk + cq + 4];
                ah[mi][3] = Ah[r + 8][kk + cq + 4];
                al[mi][0] = Al[r][kk + cq];
                al[mi][1] = Al[r + 8][kk + cq];
                al[mi][2] = Al[r][kk + cq + 4];
                al[mi][3] = Al[r + 8][kk + cq + 4];
            }
            #pragma unroll
            for (int ni = 0; ni < 4; ni++) {
                int n = wn * 32 + ni * 8 + rq;
                bf[ni][0] = Bs[kk + cq][n];
                bf[ni][1] = Bs[kk + cq + 4][n];
            }
            #pragma unroll
            for (int mi = 0; mi < 2; mi++)
                #pragma unroll
                for (int ni = 0; ni < 4; ni++) {
                    mma_tf32(acc[mi][ni], ah[mi], bf[ni]);
                    mma_tf32(acc[mi][ni], al[mi], bf[ni]);
                }
        }
    }

    #pragma unroll
    for (int mi = 0; mi < 2; mi++) {
        #pragma unroll
        for (int ni = 0; ni < 4; ni++) {
            int ncol = wn * 32 + ni * 8 + cq * 2;
            float bx = bias[n0 + ncol];
            float by = bias[n0 + ncol + 1];
            int m = m0 + wm * 32 + mi * 16 + rq;
            {
                int b = m >> 10, s = m & (SQ - 1);
                float* dst = out + ((size_t)((b * NH + h) * SQ + s)) * DK + ncol;
                *(float2*)dst = make_float2((acc[mi][ni][0] + bx) * scale,
                                            (acc[mi][ni][1] + by) * scale);
            }
            {
                int m2 = m + 8;
                int b = m2 >> 10, s = m2 & (SQ - 1);
                float* dst = out + ((size_t)((b * NH + h) * SQ + s)) * DK + ncol;
                *(float2*)dst = make_float2((acc[mi][ni][2] + bx) * scale,
                                            (acc[mi][ni][3] + by) * scale);
            }
        }
    }
}

// =====================================================================
// K2: scores = q @ k^T per (b,h) via tf32 mma. CTA tile 128x128.
// grid (8, 8, 24), dyn smem 69632 B.
// =====================================================================
__global__ __launch_bounds__(256) void k_qk()
{
    extern __shared__ __align__(16) u32 smu[];
    u32 (*Qs)[68] = (u32(*)[68])smu;
    u32 (*Ks)[68] = (u32(*)[68])(smu + 128 * 68);

    const int bh = blockIdx.z;
    const float* Aq = g_q + (size_t)bh * SQ * DK;
    const float* Bk = g_k + (size_t)bh * SQ * DK;
    float* C = g_scores + (size_t)bh * SQ * SQ;

    const int m0 = blockIdx.x * 128;
    const int n0 = blockIdx.y * 128;
    const int tid = threadIdx.x;
    const int lane = tid & 31;
    const int warp = tid >> 5;
    const int wm = warp >> 2;
    const int wn = warp & 3;
    const int rq = lane >> 2;
    const int cq = lane & 3;

    #pragma unroll
    for (int it = 0; it < 8; it++) {
        int f = tid + it * 256;
        int r  = f >> 4;
        int d4 = (f & 15) * 4;
        float4 va = *(const float4*)(Aq + (size_t)(m0 + r) * DK + d4);
        float4 vb = *(const float4*)(Bk + (size_t)(n0 + r) * DK + d4);
        *(uint4*)&Qs[r][d4] = cvt4(va);
        *(uint4*)&Ks[r][d4] = cvt4(vb);
    }
    __syncthreads();

    float acc[4][4][4];
    #pragma unroll
    for (int i = 0; i < 4; i++)
        #pragma unroll
        for (int j = 0; j < 4; j++)
            #pragma unroll
            for (int t = 0; t < 4; t++) acc[i][j][t] = 0.f;

    #pragma unroll
    for (int ks = 0; ks < 8; ks++) {
        int d0 = ks * 8;
        u32 a[4][4], bf[4][2];
        #pragma unroll
        for (int mi = 0; mi < 4; mi++) {
            int r = wm * 64 + mi * 16 + rq;
            a[mi][0] = Qs[r][d0 + cq];
            a[mi][1] = Qs[r + 8][d0 + cq];
            a[mi][2] = Qs[r][d0 + cq + 4];
            a[mi][3] = Qs[r + 8][d0 + cq + 4];
        }
        #pragma unroll
        for (int ni = 0; ni < 4; ni++) {
            int n = wn * 32 + ni * 8 + rq;
            bf[ni][0] = Ks[n][d0 + cq];
            bf[ni][1] = Ks[n][d0 + cq + 4];
        }
        #pragma unroll
        for (int mi = 0; mi < 4; mi++)
            #pragma unroll
            for (int ni = 0; ni < 4; ni++)
                mma_tf32(acc[mi][ni], a[mi], bf[ni]);
    }

    #pragma unroll
    for (int mi = 0; mi < 4; mi++) {
        #pragma unroll
        for (int ni = 0; ni < 4; ni++) {
            int r0 = m0 + wm * 64 + mi * 16 + rq;
            int c0 = n0 + wn * 32 + ni * 8 + cq * 2;
            *(float2*)(C + (size_t)r0 * SQ + c0)       = make_float2(acc[mi][ni][0], acc[mi][ni][1]);
            *(float2*)(C + (size_t)(r0 + 8) * SQ + c0) = make_float2(acc[mi][ni][2], acc[mi][ni][3]);
        }
    }
}

// =====================================================================
// K3 (fused): per (b,q): scores += q . relation_k (tf32 mma), softmax.
// 512 threads = 16 warps; warp w handles chunk cols [w*8, w*8+8).
// grid (1024, 2), dyn smem 88064 B.
// =====================================================================
__global__ __launch_bounds__(512) void k_qrel_sm(const float* __restrict__ relk)
{
    extern __shared__ __align__(16) float sm[];
    float* ss = sm;                                        // 12*1024 floats
    u32 (*rks)[68] = (u32(*)[68])(sm + NH * SQ);           // 128*68 tf32
    u32 (*qs)[64] = (u32(*)[64])(sm + NH * SQ + 128 * 68); // 16*64 tf32 (rows 12-15 zero)

    const int b = blockIdx.y, q = blockIdx.x;
    const int tid = threadIdx.x;
    const int lane = tid & 31;
    const int warp = tid >> 5;       // 0..15
    const int rq = lane >> 2;        // 0..7
    const int cq = lane & 3;         // 0..3
    const int n0c = warp * 8;

    if (tid < 192) {
        int hh = tid >> 4;
        int d4 = (tid & 15) * 4;
        float4 v = *(const float4*)(g_q + ((size_t)((b * NH + hh) * SQ + q)) * DK + d4);
        *(uint4*)&qs[hh][d4] = cvt4(v);
    } else if (tid < 256) {
        int r = 12 + ((tid - 192) >> 4);
        int d4 = ((tid - 192) & 15) * 4;
        *(uint4*)&qs[r][d4] = make_uint4(0u, 0u, 0u, 0u);
    }
    #pragma unroll
    for (int it = 0; it < 6; it++) {
        int f = tid + it * 512;
        int hh = f >> 8;
        int k4 = (f & 255) * 4;
        *(float4*)&ss[hh * SQ + k4] =
            *(const float4*)(g_scores + ((size_t)((b * NH + hh) * SQ + q)) * SQ + k4);
    }

    const float* relbase = relk + ((size_t)(b * SQ + q)) * SQ * DK;

    float4 pf[4];
    #pragma unroll
    for (int it = 0; it < 4; it++) {
        int f = tid + it * 512;
        pf[it] = *(const float4*)(relbase + (size_t)(f >> 4) * DK + (f & 15) * 4);
    }
    __syncthreads();

    u32 afrag[8][4];
    #pragma unroll
    for (int ks = 0; ks < 8; ks++) {
        int d0 = ks * 8;
        afrag[ks][0] = qs[rq][d0 + cq];
        afrag[ks][1] = qs[rq + 8][d0 + cq];
        afrag[ks][2] = qs[rq][d0 + cq + 4];
        afrag[ks][3] = qs[rq + 8][d0 + cq + 4];
    }

    for (int kt = 0; kt < SQ; kt += 128) {
        __syncthreads();
        #pragma unroll
        for (int it = 0; it < 4; it++) {
            int f = tid + it * 512;
            *(uint4*)&rks[f >> 4][(f & 15) * 4] = cvt4(pf[it]);
        }
        __syncthreads();

        if (kt + 128 < SQ) {
            #pragma unroll
            for (int it = 0; it < 4; it++) {
                int f = tid + it * 512;
                pf[it] = *(const float4*)(relbase + (size_t)(kt + 128 + (f >> 4)) * DK + (f & 15) * 4);
            }
        }

        float acc[4] = {0.f, 0.f, 0.f, 0.f};
        #pragma unroll
        for (int ks = 0; ks < 8; ks++) {
            int d0 = ks * 8;
            u32 bf[2];
            bf[0] = rks[n0c + rq][d0 + cq];
            bf[1] = rks[n0c + rq][d0 + cq + 4];
            mma_tf32(acc, afrag[ks], bf);
        }

        int col = kt + n0c + cq * 2;
        ss[rq * SQ + col]     += acc[0];
        ss[rq * SQ + col + 1] += acc[1];
        if (rq < 4) {
            ss[(rq + 8) * SQ + col]     += acc[2];
            ss[(rq + 8) * SQ + col + 1] += acc[3];
        }
    }
    __syncthreads();

    const int swarp = tid >> 5;
    const int slane = tid & 31;
    if (swarp < NH) {
        float* p = ss + swarp * SQ;
        float4 v[8];
        float mx = -3.4e38f;
        #pragma unroll
        for (int j = 0; j < 8; j++) {
            v[j] = *(float4*)(p + slane * 4 + j * 128);
            mx = fmaxf(mx, fmaxf(fmaxf(v[j].x, v[j].y), fmaxf(v[j].z, v[j].w)));
        }
        #pragma unroll
        for (int o = 16; o > 0; o >>= 1) mx = fmaxf(mx, __shfl_xor_sync(0xffffffffu, mx, o));

        float s = 0.f;
        #pragma unroll
        for (int j = 0; j < 8; j++) {
            v[j].x = __expf(v[j].x - mx);
            v[j].y = __expf(v[j].y - mx);
            v[j].z = __expf(v[j].z - mx);
            v[j].w = __expf(v[j].w - mx);
            s += v[j].x + v[j].y + v[j].z + v[j].w;
        }
        #pragma unroll
        for (int o = 16; o > 0; o >>= 1) s += __shfl_xor_sync(0xffffffffu, s, o);
        const float inv = 1.0f / s;

        float* dst = g_scores + ((size_t)((b * NH + swarp) * SQ + q)) * SQ;
        #pragma unroll
        for (int j = 0; j < 8; j++) {
            v[j].x *= inv; v[j].y *= inv; v[j].z *= inv; v[j].w *= inv;
            *(float4*)(dst + slane * 4 + j * 128) = v[j];
        }
    }
}

// =====================================================================
// K5: wv = probs @ v per (b,h) via tf32 mma. split-K=2. grid (8,24,2).
// =====================================================================
__global__ __launch_bounds__(256) void k_wv()
{
    __shared__ __align__(16) u32 As[128][36];
    __shared__ __align__(16) u32 Bs[32][72];

    const int bh = blockIdx.y;
    const int b = bh / NH, h = bh % NH;
    const int koff = blockIdx.z * 512;
    const float* A  = g_scores + (size_t)bh * SQ * SQ + koff;
    const float* Bv = g_v + ((size_t)bh * SQ + koff) * DK;
    float* outp = blockIdx.z ? g_attn2 : g_attn;

    const int m0 = blockIdx.x * 128;
    const int tid = threadIdx.x;
    const int lane = tid & 31;
    const int warp = tid >> 5;
    const int wm = warp >> 1;
    const int wn = warp & 1;
    const int rq = lane >> 2;
    const int cq = lane & 3;

    float acc[2][4][4];
    #pragma unroll
    for (int i = 0; i < 2; i++)
        #pragma unroll
        for (int j = 0; j < 4; j++)
            #pragma unroll
            for (int t = 0; t < 4; t++) acc[i][j][t] = 0.f;

    float4 pfa[4], pfb[2];
    #pragma unroll
    for (int it = 0; it < 4; it++) {
        int f = tid + it * 256;
        pfa[it] = *(const float4*)(A + (size_t)(m0 + (f >> 3)) * SQ + (f & 7) * 4);
    }
    #pragma unroll
    for (int it = 0; it < 2; it++) {
        int f = tid + it * 256;
        pfb[it] = *(const float4*)(Bv + (size_t)(f >> 4) * DK + (f & 15) * 4);
    }

    for (int k0 = 0; k0 < 512; k0 += 32) {
        __syncthreads();
        #pragma unroll
        for (int it = 0; it < 4; it++) {
            int f = tid + it * 256;
            *(uint4*)&As[f >> 3][(f & 7) * 4] = cvt4(pfa[it]);
        }
        #pragma unroll
        for (int it = 0; it < 2; it++) {
            int f = tid + it * 256;
            *(uint4*)&Bs[f >> 4][(f & 15) * 4] = cvt4(pfb[it]);
        }
        __syncthreads();

        if (k0 + 32 < 512) {
            #pragma unroll
            for (int it = 0; it < 4; it++) {
                int f = tid + it * 256;
                pfa[it] = *(const float4*)(A + (size_t)(m0 + (f >> 3)) * SQ + k0 + 32 + (f & 7) * 4);
            }
            #pragma unroll
            for (int it = 0; it < 2; it++) {
                int f = tid + it * 256;
                pfb[it] = *(const float4*)(Bv + (size_t)(k0 + 32 + (f >> 4)) * DK + (f & 15) * 4);
            }
        }

        #pragma unroll
        for (int ks = 0; ks < 4; ks++) {
            int kk = ks * 8;
            u32 a[2][4], bf[4][2];
            #pragma unroll
            for (int mi = 0; mi < 2; mi++) {
                int r = wm * 32 + mi * 16 + rq;
                a[mi][0] = As[r][kk + cq];
                a[mi][1] = As[r + 8][kk + cq];
                a[mi][2] = As[r][kk + cq + 4];
                a[mi][3] = As[r + 8][kk + cq + 4];
            }
            #pragma unroll
            for (int ni = 0; ni < 4; ni++) {
                int n = wn * 32 + ni * 8 + rq;
                bf[ni][0] = Bs[kk + cq][n];
                bf[ni][1] = Bs[kk + cq + 4][n];
            }
            #pragma unroll
            for (int mi = 0; mi < 2; mi++)
                #pragma unroll
                for (int ni = 0; ni < 4; ni++)
                    mma_tf32(acc[mi][ni], a[mi], bf[ni]);
        }
    }

    #pragma unroll
    for (int mi = 0; mi < 2; mi++) {
        #pragma unroll
        for (int ni = 0; ni < 4; ni++) {
            int r0 = m0 + wm * 32 + mi * 16 + rq;
            int c0 = wn * 32 + ni * 8 + cq * 2;
            float* dst0 = outp + (size_t)(b * SQ + r0) * DM + h * DK + c0;
            float* dst1 = outp + (size_t)(b * SQ + r0 + 8) * DM + h * DK + c0;
            *(float2*)dst0 = make_float2(acc[mi][ni][0], acc[mi][ni][1]);
            *(float2*)dst1 = make_float2(acc[mi][ni][2], acc[mi][ni][3]);
        }
    }
}

// =====================================================================
// K6: g_attn = g_attn + g_attn2 + probs @ relation_v via tf32 mma.
// grid (1024, 2).
// =====================================================================
__global__ __launch_bounds__(256) void k_wrel(const float* __restrict__ relv)
{
    __shared__ __align__(16) u32 rvs[128][72];
    __shared__ __align__(16) u32 ps[16][132];

    const int b = blockIdx.y, q = blockIdx.x;
    const int tid = threadIdx.x;
    const int lane = tid & 31;
    const int warp = tid >> 5;
    const int rq = lane >> 2;
    const int cq = lane & 3;
    const int n0c = warp * 8;

    {
        int r = 12 + (tid >> 6);
        int c = (tid & 63) * 2;
        ps[r][c] = 0u; ps[r][c + 1] = 0u;
    }

    const float* relbase = relv + ((size_t)(b * SQ + q)) * SQ * DK;
    const float* psrc = g_scores + ((size_t)(b * NH) * SQ + q) * SQ;

    float acc[4] = {0.f, 0.f, 0.f, 0.f};

    float4 pfr[8], pfp[2];
    #pragma unroll
    for (int it = 0; it < 8; it++) {
        int f = tid + it * 256;
        pfr[it] = *(const float4*)(relbase + (size_t)(f >> 4) * DK + (f & 15) * 4);
    }
    #pragma unroll
    for (int it = 0; it < 2; it++) {
        int f = tid + it * 256;
        if (f < 384)
            pfp[it] = *(const float4*)(psrc + (size_t)(f >> 5) * SQ * SQ + (f & 31) * 4);
    }

    for (int kt = 0; kt < SQ; kt += 128) {
        __syncthreads();
        #pragma unroll
        for (int it = 0; it < 8; it++) {
            int f = tid + it * 256;
            *(uint4*)&rvs[f >> 4][(f & 15) * 4] = cvt4(pfr[it]);
        }
        #pragma unroll
        for (int it = 0; it < 2; it++) {
            int f = tid + it * 256;
            if (f < 384)
                *(uint4*)&ps[f >> 5][(f & 31) * 4] = cvt4(pfp[it]);
        }
        __syncthreads();

        if (kt + 128 < SQ) {
            #pragma unroll
            for (int it = 0; it < 8; it++) {
                int f = tid + it * 256;
                pfr[it] = *(const float4*)(relbase + (size_t)(kt + 128 + (f >> 4)) * DK + (f & 15) * 4);
            }
            #pragma unroll
            for (int it = 0; it < 2; it++) {
                int f = tid + it * 256;
                if (f < 384)
                    pfp[it] = *(const float4*)(psrc + (size_t)(f >> 5) * SQ * SQ + kt + 128 + (f & 31) * 4);
            }
        }

        #pragma unroll
        for (int ks = 0; ks < 16; ks++) {
            int kk = ks * 8;
            u32 a[4], bf[2];
            a[0] = ps[rq][kk + cq];
            a[1] = ps[rq + 8][kk + cq];
            a[2] = ps[rq][kk + cq + 4];
            a[3] = ps[rq + 8][kk + cq + 4];
            bf[0] = rvs[kk + cq][n0c + rq];
            bf[1] = rvs[kk + cq + 4][n0c + rq];
            mma_tf32(acc, a, bf);
        }
    }

    const size_t base = (size_t)(b * SQ + q) * DM;
    const int col = n0c + cq * 2;
    {
        size_t idx = base + rq * DK + col;
        float2 a1 = *(const float2*)(g_attn + idx);
        float2 a2 = *(const float2*)(g_attn2 + idx);
        *(float2*)(g_attn + idx) = make_float2(acc[0] + a1.x + a2.x, acc[1] + a1.y + a2.y);
    }
    if (rq < 4) {
        size_t idx = base + (rq + 8) * DK + col;
        float2 a1 = *(const float2*)(g_attn + idx);
        float2 a2 = *(const float2*)(g_attn2 + idx);
        *(float2*)(g_attn + idx) = make_float2(acc[2] + a1.x + a2.x, acc[3] + a1.y + a2.y);
    }
}

// =====================================================================
// K7: output projection via tf32 mma (plain). BM=128, BN=64, BK=32.
// 256 threads, warp grid 4(m)x2(n). grid (16, 12).
// =====================================================================
__global__ __launch_bounds__(256) void k_out(
    const float* __restrict__ Wo, const float* __restrict__ bo, float* __restrict__ out)
{
    __shared__ __align__(16) u32 As[128][36];
    __shared__ __align__(16) u32 Bs[32][72];

    const int tid = threadIdx.x;
    const int lane = tid & 31;
    const int warp = tid >> 5;
    const int wm = warp >> 1;
    const int wn = warp & 1;
    const int rq = lane >> 2;
    const int cq = lane & 3;
    const int m0 = blockIdx.x * 128;
    const int n0 = blockIdx.y * 64;

    float acc[2][4][4];
    #pragma unroll
    for (int i = 0; i < 2; i++)
        #pragma unroll
        for (int j = 0; j < 4; j++)
            #pragma unroll
            for (int t = 0; t < 4; t++) acc[i][j][t] = 0.f;

    float4 pfa[4], pfb[2];
    #pragma unroll
    for (int it = 0; it < 4; it++) {
        int f = tid + it * 256;
        pfa[it] = *(const float4*)(g_attn + (size_t)(m0 + (f >> 3)) * DM + (f & 7) * 4);
    }
    #pragma unroll
    for (int it = 0; it < 2; it++) {
        int f = tid + it * 256;
        pfb[it] = *(const float4*)(Wo + (size_t)(f >> 4) * DM + n0 + (f & 15) * 4);
    }

    for (int k0 = 0; k0 < DM; k0 += 32) {
        __syncthreads();
        #pragma unroll
        for (int it = 0; it < 4; it++) {
            int f = tid + it * 256;
            *(uint4*)&As[f >> 3][(f & 7) * 4] = cvt4(pfa[it]);
        }
        #pragma unroll
        for (int it = 0; it < 2; it++) {
            int f = tid + it * 256;
            *(uint4*)&Bs[f >> 4][(f & 15) * 4] = cvt4(pfb[it]);
        }
        __syncthreads();

        if (k0 + 32 < DM) {
            #pragma unroll
            for (int it = 0; it < 4; it++) {
                int f = tid + it * 256;
                pfa[it] = *(const float4*)(g_attn + (size_t)(m0 + (f >> 3)) * DM + k0 + 32 + (f & 7) * 4);
            }
            #pragma unroll
            for (int it = 0; it < 2; it++) {
                int f = tid + it * 256;
                pfb[it] = *(const float4*)(Wo + (size_t)(k0 + 32 + (f >> 4)) * DM + n0 + (f & 15) * 4);
            }
        }

        #pragma unroll
        for (int ks = 0; ks < 4; ks++) {
            int kk = ks * 8;
            u32 a[2][4], bf[4][2];
            #pragma unroll
            for (int mi = 0; mi < 2; mi++) {
                int r = wm * 32 + mi * 16 + rq;
                a[mi][0] = As[r][kk + cq];
                a[mi][1] = As[r + 8][kk + cq];
                a[mi][2] = As[r][kk + cq + 4];
                a[mi][3] = As[r + 8][kk + cq + 4];
            }
            #pragma unroll
            for (int ni = 0; ni < 4; ni++) {
                int n = wn * 32 + ni * 8 + rq;
                bf[ni][0] = Bs[kk + cq][n];
                bf[ni][1] = Bs[kk + cq + 4][n];
            }
            #pragma unroll
            for (int mi = 0; mi < 2; mi++)
                #pragma unroll
                for (int ni = 0; ni < 4; ni++)
                    mma_tf32(acc[mi][ni], a[mi], bf[ni]);
        }
    }

    #pragma unroll
    for (int mi = 0; mi < 2; mi++) {
        #pragma unroll
        for (int ni = 0; ni < 4; ni++) {
            int ncol = wn * 32 + ni * 8 + cq * 2;
            float bx = bo[n0 + ncol];
            float by = bo[n0 + ncol + 1];
            int m = m0 + wm * 32 + mi * 16 + rq;
            *(float2*)(out + (size_t)m * DM + n0 + ncol) =
                make_float2(acc[mi][ni][0] + bx, acc[mi][ni][1] + by);
            *(float2*)(out + (size_t)(m + 8) * DM + n0 + ncol) =
                make_float2(acc[mi][ni][2] + bx, acc[mi][ni][3] + by);
        }
    }
}

// =====================================================================
extern "C" void kernel_launch(void* const* d_in, const int* in_sizes, int n_in,
                              void* d_out, int out_size)
{
    const float* queries = (const float*)d_in[0];
    const float* keys    = (const float*)d_in[1];
    const float* values  = (const float*)d_in[2];
    const float* relk    = (const float*)d_in[3];
    const float* relv    = (const float*)d_in[4];
    const float* Wq = (const float*)d_in[5];
    const float* bq = (const float*)d_in[6];
    const float* Wk = (const float*)d_in[7];
    const float* bk = (const float*)d_in[8];
    const float* Wv = (const float*)d_in[9];
    const float* bv = (const float*)d_in[10];
    const float* Wo = (const float*)d_in[11];
    const float* bo = (const float*)d_in[12];
    float* out = (float*)d_out;

    const int qrel_smem = NH * SQ * (int)sizeof(float)
                        + 128 * 68 * (int)sizeof(u32)
                        + 16 * 64 * (int)sizeof(u32);

    static bool attr_set = false;
    if (!attr_set) {
        cudaFuncSetAttribute(k_qk, cudaFuncAttributeMaxDynamicSharedMemorySize,
                             2 * 128 * 68 * (int)sizeof(u32));
        cudaFuncSetAttribute(k_qrel_sm, cudaFuncAttributeMaxDynamicSharedMemorySize,
                             qrel_smem);
        attr_set = true;
    }

    k_proj<<<dim3(16, 12, 3), 256>>>(queries, keys, values, Wq, Wk, Wv, bq, bk, bv);
    k_qk<<<dim3(8, 8, NB * NH), 256, 2 * 128 * 68 * sizeof(u32)>>>();
    k_qrel_sm<<<dim3(SQ, NB), 512, qrel_smem>>>(relk);
    k_wv<<<dim3(8, NB * NH, 2), 256>>>();
    k_wrel<<<dim3(SQ, NB), 256>>>(relv);
    k_out<<<dim3(16, 12), 256>>>(Wo, bo, out);
}